// round 5
// baseline (speedup 1.0000x reference)
#include <cuda_runtime.h>
#include <cuda_bf16.h>
#include <math.h>
#include <stdint.h>

#define D_MODEL 1024
#define N_HEADS 16
#define HEAD_DIM 64
#define BATCH 4
#define SEQ 2048
#define M_ROWS (BATCH * SEQ)          // 8192
#define QKV_N (3 * D_MODEL)           // 3072

// ======================= scratch (static device globals) =======================
__device__ __align__(16) float g_Q[BATCH * N_HEADS * SEQ * HEAD_DIM];
__device__ __align__(16) float g_K[BATCH * N_HEADS * SEQ * HEAD_DIM];
__device__ __align__(16) float g_V[BATCH * N_HEADS * SEQ * HEAD_DIM];
__device__ __align__(16) float g_cos[SEQ * 32];
__device__ __align__(16) float g_sin[SEQ * 32];
__device__ __align__(16) __nv_bfloat16 g_xhi[M_ROWS * D_MODEL];
__device__ __align__(16) __nv_bfloat16 g_xlo[M_ROWS * D_MODEL];
__device__ __align__(16) __nv_bfloat16 g_wqh[D_MODEL * QKV_N];
__device__ __align__(16) __nv_bfloat16 g_wql[D_MODEL * QKV_N];
__device__ __align__(16) __nv_bfloat16 g_aoh[M_ROWS * D_MODEL];
__device__ __align__(16) __nv_bfloat16 g_aol[M_ROWS * D_MODEL];
__device__ __align__(16) __nv_bfloat16 g_woh[D_MODEL * D_MODEL];
__device__ __align__(16) __nv_bfloat16 g_wol[D_MODEL * D_MODEL];
__device__ __align__(16) __nv_bfloat16 g_qh[BATCH * N_HEADS * SEQ * HEAD_DIM];
__device__ __align__(16) __nv_bfloat16 g_ql[BATCH * N_HEADS * SEQ * HEAD_DIM];
__device__ __align__(16) __nv_bfloat16 g_kh[BATCH * N_HEADS * SEQ * HEAD_DIM];
__device__ __align__(16) __nv_bfloat16 g_kl[BATCH * N_HEADS * SEQ * HEAD_DIM];
__device__ __align__(16) __nv_bfloat16 g_vh[BATCH * N_HEADS * SEQ * HEAD_DIM];
__device__ __align__(16) __nv_bfloat16 g_vl[BATCH * N_HEADS * SEQ * HEAD_DIM];

// ======================= PTX helpers =======================
__device__ __forceinline__ uint32_t smem_to_u32(const void* smem_ptr) {
    uint32_t addr;
    asm("{ .reg .u64 tmp; cvta.to.shared.u64 tmp, %1; cvt.u32.u64 %0, tmp; }"
        : "=r"(addr) : "l"(smem_ptr));
    return addr;
}
__device__ __forceinline__ void cpa16(uint32_t s, const void* g) {
    asm volatile("cp.async.cg.shared.global [%0], [%1], 16;" :: "r"(s), "l"(g));
}
__device__ __forceinline__ void cpa_commit() {
    asm volatile("cp.async.commit_group;" ::: "memory");
}
__device__ __forceinline__ void ldsm4(uint32_t* r, uint32_t addr) {
    asm volatile("ldmatrix.sync.aligned.m8n8.x4.shared.b16 {%0,%1,%2,%3}, [%4];"
        : "=r"(r[0]), "=r"(r[1]), "=r"(r[2]), "=r"(r[3]) : "r"(addr));
}
__device__ __forceinline__ void ldsm4t(uint32_t* r, uint32_t addr) {
    asm volatile("ldmatrix.sync.aligned.m8n8.x4.trans.shared.b16 {%0,%1,%2,%3}, [%4];"
        : "=r"(r[0]), "=r"(r[1]), "=r"(r[2]), "=r"(r[3]) : "r"(addr));
}
// NON-volatile: pure reg in/out, lets ptxas schedule/interleave MMAs
__device__ __forceinline__ void mma16816(float* c, const uint32_t* a, uint32_t b0, uint32_t b1) {
    asm("mma.sync.aligned.m16n8k16.row.col.f32.bf16.bf16.f32 "
        "{%0,%1,%2,%3}, {%4,%5,%6,%7}, {%8,%9}, {%0,%1,%2,%3};"
        : "+f"(c[0]), "+f"(c[1]), "+f"(c[2]), "+f"(c[3])
        : "r"(a[0]), "r"(a[1]), "r"(a[2]), "r"(a[3]), "r"(b0), "r"(b1));
}
__device__ __forceinline__ uint32_t pack_bf16x2(float a, float b) {
    __nv_bfloat162 h = __floats2bfloat162_rn(a, b);
    return *(uint32_t*)&h;
}
__device__ __forceinline__ float ex2f(float x) {
    float r;
    asm("ex2.approx.ftz.f32 %0, %1;" : "=f"(r) : "f"(x));
    return r;
}

// ======================= RoPE table =======================
__global__ void rope_table_kernel() {
    int t = blockIdx.x;
    int i = threadIdx.x;
    double inv = pow(10000.0, -((double)(2 * i)) / 64.0);
    double a = (double)t * inv;
    g_cos[t * 32 + i] = (float)cos(a);
    g_sin[t * 32 + i] = (float)sin(a);
}

// ======================= fp32 -> bf16 hi/lo split =======================
__global__ void conv_split_kernel(const float* __restrict__ in,
                                  __nv_bfloat16* __restrict__ hi,
                                  __nv_bfloat16* __restrict__ lo, int n) {
    int i = blockIdx.x * blockDim.x + threadIdx.x;
    int stride = gridDim.x * blockDim.x;
    for (; i < n; i += stride) {
        float v = in[i];
        __nv_bfloat16 h = __float2bfloat16(v);
        hi[i] = h;
        lo[i] = __float2bfloat16(v - __bfloat162float(h));
    }
}

// ======================= transpose + split =======================
__global__ void trans_split_kernel(const float* __restrict__ W,
                                   __nv_bfloat16* __restrict__ Thi,
                                   __nv_bfloat16* __restrict__ Tlo,
                                   int K, int N) {
    __shared__ float t[32][33];
    int n = blockIdx.x * 32 + threadIdx.x;
    int k0 = blockIdx.y * 32;
#pragma unroll
    for (int r = 0; r < 32; r += 8)
        t[threadIdx.y + r][threadIdx.x] = W[(size_t)(k0 + threadIdx.y + r) * N + n];
    __syncthreads();
    int k = k0 + threadIdx.x;
#pragma unroll
    for (int r = 0; r < 32; r += 8) {
        int n2 = blockIdx.x * 32 + threadIdx.y + r;
        float v = t[threadIdx.x][threadIdx.y + r];
        __nv_bfloat16 h = __float2bfloat16(v);
        Thi[(size_t)n2 * K + k] = h;
        Tlo[(size_t)n2 * K + k] = __float2bfloat16(v - __bfloat162float(h));
    }
}

// ======================= warp-MMA GEMM (term-major MMA order) =======================
#define TILE_B   10240
#define STG_B    (4 * TILE_B)
#define GEMM_SMEM (2 * STG_B)

__device__ __forceinline__ void load_stage(
    uint32_t sb, const __nv_bfloat16* __restrict__ Ahi, const __nv_bfloat16* __restrict__ Alo,
    const __nv_bfloat16* __restrict__ Bhi, const __nv_bfloat16* __restrict__ Blo,
    int m0, int n0, int k0, int tid)
{
    const __nv_bfloat16* gp[4] = { Ahi, Alo, Bhi, Blo };
    int rb[4] = { m0, m0, n0, n0 };
#pragma unroll
    for (int tlb = 0; tlb < 4; tlb++) {
#pragma unroll
        for (int h = 0; h < 2; h++) {
            int ch = tid + h * 256;
            int row = ch >> 2, c16 = ch & 3;
            cpa16(sb + tlb * TILE_B + row * 80 + c16 * 16,
                  gp[tlb] + (size_t)(rb[tlb] + row) * 1024 + k0 + c16 * 8);
        }
    }
}

template <int EPI>
__global__ void __launch_bounds__(256, 2) gemm_mma_kernel(
    const __nv_bfloat16* __restrict__ Ahi, const __nv_bfloat16* __restrict__ Alo,
    const __nv_bfloat16* __restrict__ Bhi, const __nv_bfloat16* __restrict__ Blo,
    float* __restrict__ Cout)
{
    extern __shared__ char dsm[];
    uint32_t sb0 = smem_to_u32(dsm);
    int tid = threadIdx.x, lane = tid & 31, wid = tid >> 5;
    int warpM = wid >> 2, warpN = wid & 3;
    int m0 = blockIdx.y * 128, n0 = blockIdx.x * 128;

    float c[4][4][4];
#pragma unroll
    for (int i = 0; i < 4; i++)
#pragma unroll
        for (int j = 0; j < 4; j++)
#pragma unroll
            for (int k = 0; k < 4; k++) c[i][j][k] = 0.f;

    uint32_t aRow = (uint32_t)((warpM * 64 + (lane & 15)) * 80 + ((lane >> 4) << 4));
    uint32_t bRow = (uint32_t)((warpN * 32 + ((lane >> 4) << 3) + (lane & 7)) * 80 +
                               (((lane >> 3) & 1) << 4));

    const int NS = 32;
    load_stage(sb0, Ahi, Alo, Bhi, Blo, m0, n0, 0, tid);
    cpa_commit();

    for (int s = 0; s < NS; s++) {
        uint32_t sb = sb0 + (uint32_t)((s & 1) * STG_B);
        if (s + 1 < NS) {
            load_stage(sb0 + (uint32_t)(((s + 1) & 1) * STG_B),
                       Ahi, Alo, Bhi, Blo, m0, n0, (s + 1) * 32, tid);
            cpa_commit();
            asm volatile("cp.async.wait_group 1;" ::: "memory");
        } else {
            asm volatile("cp.async.wait_group 0;" ::: "memory");
        }
        __syncthreads();

#pragma unroll
        for (int k16 = 0; k16 < 2; k16++) {
            uint32_t koff = (uint32_t)(k16 * 32);
            uint32_t ah[4][4], al[4][4], bh[2][4], bl[2][4];
#pragma unroll
            for (int mf = 0; mf < 4; mf++) {
                uint32_t a = sb + aRow + (uint32_t)(mf * 1280) + koff;
                ldsm4(ah[mf], a);
                ldsm4(al[mf], a + TILE_B);
            }
#pragma unroll
            for (int nf2 = 0; nf2 < 2; nf2++) {
                uint32_t b = sb + 2 * TILE_B + bRow + (uint32_t)(nf2 * 1280) + koff;
                ldsm4(bh[nf2], b);
                ldsm4(bl[nf2], b + TILE_B);
            }
            // term-major: 16 independent accumulators per sweep -> no RAW stalls
#pragma unroll
            for (int mf = 0; mf < 4; mf++)
#pragma unroll
                for (int nf = 0; nf < 4; nf++)
                    mma16816(c[mf][nf], ah[mf],
                             bh[nf >> 1][(nf & 1) * 2], bh[nf >> 1][(nf & 1) * 2 + 1]);
#pragma unroll
            for (int mf = 0; mf < 4; mf++)
#pragma unroll
                for (int nf = 0; nf < 4; nf++)
                    mma16816(c[mf][nf], ah[mf],
                             bl[nf >> 1][(nf & 1) * 2], bl[nf >> 1][(nf & 1) * 2 + 1]);
#pragma unroll
            for (int mf = 0; mf < 4; mf++)
#pragma unroll
                for (int nf = 0; nf < 4; nf++)
                    mma16816(c[mf][nf], al[mf],
                             bh[nf >> 1][(nf & 1) * 2], bh[nf >> 1][(nf & 1) * 2 + 1]);
        }
        __syncthreads();
    }

    int mBase = m0 + warpM * 64 + (lane >> 2);
    int nBase = n0 + warpN * 32 + (lane & 3) * 2;
#pragma unroll
    for (int mf = 0; mf < 4; mf++) {
#pragma unroll
        for (int nf = 0; nf < 4; nf++) {
            int row = mBase + mf * 16;
            int col = nBase + nf * 8;
            if (EPI == 0) {
                int sel = col >> 10, h = (col >> 6) & 15, d = col & 63;
                int b = row >> 11, t = row & 2047;
                float* base = (sel == 0 ? g_Q : (sel == 1 ? g_K : g_V)) +
                              ((size_t)((b * 16 + h) * 2048)) * 64 + d;
                *(float2*)(base + (size_t)t * 64) =
                    make_float2(c[mf][nf][0], c[mf][nf][1]);
                *(float2*)(base + (size_t)(t + 8) * 64) =
                    make_float2(c[mf][nf][2], c[mf][nf][3]);
            } else {
                *(float2*)(Cout + (size_t)row * 1024 + col) =
                    make_float2(c[mf][nf][0], c[mf][nf][1]);
                *(float2*)(Cout + (size_t)(row + 8) * 1024 + col) =
                    make_float2(c[mf][nf][2], c[mf][nf][3]);
            }
        }
    }
}

// ======================= RoPE + bf16 hi/lo split of Q (scaled) and K =======================
__global__ void rope_split_kernel() {
    int idx = blockIdx.x * blockDim.x + threadIdx.x;
    int i = idx & 31;
    int t = (idx >> 5) & 2047;
    int bh = (idx >> 16) & 63;
    int which = idx >> 22;
    size_t base = ((size_t)bh * 2048 + t) * 64;
    float c = g_cos[t * 32 + i];
    float s = g_sin[t * 32 + i];
    const float* X = which ? g_K : g_Q;
    float x1 = X[base + i];
    float x2 = X[base + i + 32];
    float r1 = x1 * c - x2 * s;
    float r2 = x2 * c + x1 * s;
    if (which == 0) {
        const float SC = 0.125f * 1.44269504088896f;
        r1 *= SC; r2 *= SC;
        __nv_bfloat16 h1 = __float2bfloat16(r1);
        __nv_bfloat16 h2 = __float2bfloat16(r2);
        g_qh[base + i] = h1;
        g_qh[base + i + 32] = h2;
        g_ql[base + i] = __float2bfloat16(r1 - __bfloat162float(h1));
        g_ql[base + i + 32] = __float2bfloat16(r2 - __bfloat162float(h2));
    } else {
        __nv_bfloat16 h1 = __float2bfloat16(r1);
        __nv_bfloat16 h2 = __float2bfloat16(r2);
        g_kh[base + i] = h1;
        g_kh[base + i + 32] = h2;
        g_kl[base + i] = __float2bfloat16(r1 - __bfloat162float(h1));
        g_kl[base + i + 32] = __float2bfloat16(r2 - __bfloat162float(h2));
    }
}

// ======================= Tensor-core flash attention =======================
#define FRS 144
#define FTILE (64 * FRS)
#define FQ_B  (128 * FRS)
#define FSB_Q 0
#define FSB_KV (2 * FQ_B)
#define FSTG_B (4 * FTILE)
#define FLASH_SMEM (FSB_KV + 2 * FSTG_B)

__device__ __forceinline__ void flash_load_q(uint32_t sb, int bh, int q0, int tid) {
#pragma unroll
    for (int i = 0; i < 8; i++) {
        int ch = tid + i * 256;
        int tl = ch >> 10;
        int r = (ch >> 3) & 127, c16 = ch & 7;
        const __nv_bfloat16* src = (tl ? g_ql : g_qh) +
            ((size_t)bh * SEQ + q0 + r) * 64 + c16 * 8;
        cpa16(sb + FSB_Q + tl * FQ_B + r * FRS + c16 * 16, src);
    }
}
__device__ __forceinline__ void flash_load_kv(uint32_t sb, int bh, int kbase, int stg, int tid) {
    uint32_t d0 = sb + FSB_KV + stg * FSTG_B;
#pragma unroll
    for (int i = 0; i < 8; i++) {
        int ch = tid + i * 256;
        int tl = ch >> 9;
        int r = (ch >> 3) & 63, c16 = ch & 7;
        const __nv_bfloat16* base = (tl == 0) ? g_kh : (tl == 1) ? g_kl :
                                    (tl == 2) ? g_vh : g_vl;
        cpa16(d0 + tl * FTILE + r * FRS + c16 * 16,
              base + ((size_t)bh * SEQ + kbase + r) * 64 + c16 * 8);
    }
}

__global__ void __launch_bounds__(256, 1) flash_tc_kernel() {
    extern __shared__ char dsm[];
    uint32_t sb = smem_to_u32(dsm);
    int tid = threadIdx.x, lane = tid & 31, w = tid >> 5;
    int qt = 15 - (int)blockIdx.x;
    int bh = blockIdx.y;
    int q0 = qt * 128;
    int nkt = qt * 2 + 2;

    flash_load_q(sb, bh, q0, tid);
    flash_load_kv(sb, bh, 0, 0, tid);
    cpa_commit();

    uint32_t aQh[4][4], aQl[4][4];
    float o[8][4];
#pragma unroll
    for (int i = 0; i < 8; i++)
#pragma unroll
        for (int j = 0; j < 4; j++) o[i][j] = 0.f;
    float lsA = 0.f, lsB = 0.f;

    uint32_t qAddr = (uint32_t)((w * 16 + (lane & 15)) * FRS + ((lane >> 4) << 4));
    uint32_t kLane = (uint32_t)((((lane >> 4) << 3) + (lane & 7)) * FRS + (((lane >> 3) & 1) << 4));
    uint32_t vLane = (uint32_t)(((lane & 7) + ((lane >> 3) & 1) * 8) * FRS + ((lane >> 4) << 4));

    for (int kt = 0; kt < nkt; kt++) {
        if (kt + 1 < nkt) {
            flash_load_kv(sb, bh, (kt + 1) * 64, (kt + 1) & 1, tid);
            cpa_commit();
            asm volatile("cp.async.wait_group 1;" ::: "memory");
        } else {
            asm volatile("cp.async.wait_group 0;" ::: "memory");
        }
        __syncthreads();

        if (kt == 0) {
#pragma unroll
            for (int kk = 0; kk < 4; kk++) {
                uint32_t a = sb + FSB_Q + qAddr + kk * 32;
                ldsm4(aQh[kk], a);
                ldsm4(aQl[kk], a + FQ_B);
            }
        }

        uint32_t stg = sb + FSB_KV + (kt & 1) * FSTG_B;
        int kbase = kt * 64;

        // ---- S = Q K^T, term-major per kk ----
        float c[8][4];
#pragma unroll
        for (int i = 0; i < 8; i++)
#pragma unroll
            for (int j = 0; j < 4; j++) c[i][j] = 0.f;

#pragma unroll
        for (int kk = 0; kk < 4; kk++) {
            uint32_t bKh[4][4], bKl[4][4];
#pragma unroll
            for (int nf2 = 0; nf2 < 4; nf2++) {
                uint32_t ba = stg + (uint32_t)(nf2 * 16 * FRS) + kLane + kk * 32;
                ldsm4(bKh[nf2], ba);
                ldsm4(bKl[nf2], ba + FTILE);
            }
#pragma unroll
            for (int nf = 0; nf < 8; nf++)
                mma16816(c[nf], aQh[kk],
                         bKh[nf >> 1][(nf & 1) * 2], bKh[nf >> 1][(nf & 1) * 2 + 1]);
#pragma unroll
            for (int nf = 0; nf < 8; nf++)
                mma16816(c[nf], aQh[kk],
                         bKl[nf >> 1][(nf & 1) * 2], bKl[nf >> 1][(nf & 1) * 2 + 1]);
#pragma unroll
            for (int nf = 0; nf < 8; nf++)
                mma16816(c[nf], aQl[kk],
                         bKh[nf >> 1][(nf & 1) * 2], bKh[nf >> 1][(nf & 1) * 2 + 1]);
        }

        // ---- mask + exp + pack P ----
        bool needmask = (kbase + 63) > (q0 + w * 16);
        int qrA = q0 + w * 16 + (lane >> 2);
        uint32_t aPh[4][4], aPl[4][4];
#pragma unroll
        for (int nf = 0; nf < 8; nf++) {
            if (needmask) {
                int key0 = kbase + nf * 8 + (lane & 3) * 2;
                if (key0 > qrA)         c[nf][0] = -100000.f;
                if (key0 + 1 > qrA)     c[nf][1] = -100000.f;
                if (key0 > qrA + 8)     c[nf][2] = -100000.f;
                if (key0 + 1 > qrA + 8) c[nf][3] = -100000.f;
            }
            float p0 = ex2f(c[nf][0]), p1 = ex2f(c[nf][1]);
            float p2 = ex2f(c[nf][2]), p3 = ex2f(c[nf][3]);
            lsA += p0 + p1;
            lsB += p2 + p3;
            __nv_bfloat16 h0 = __float2bfloat16(p0), h1 = __float2bfloat16(p1);
            __nv_bfloat16 h2 = __float2bfloat16(p2), h3 = __float2bfloat16(p3);
            int kk = nf >> 1, sl = (nf & 1) * 2;
            aPh[kk][sl]     = ((uint32_t)*(uint16_t*)&h0) | (((uint32_t)*(uint16_t*)&h1) << 16);
            aPh[kk][sl + 1] = ((uint32_t)*(uint16_t*)&h2) | (((uint32_t)*(uint16_t*)&h3) << 16);
            aPl[kk][sl]     = pack_bf16x2(p0 - __bfloat162float(h0), p1 - __bfloat162float(h1));
            aPl[kk][sl + 1] = pack_bf16x2(p2 - __bfloat162float(h2), p3 - __bfloat162float(h3));
        }

        // ---- O += P V, term-major per kk ----
        uint32_t vstg = stg + 2 * FTILE;
#pragma unroll
        for (int kk = 0; kk < 4; kk++) {
            uint32_t vh[4][4], vl[4][4];
#pragma unroll
            for (int df2 = 0; df2 < 4; df2++) {
                uint32_t va = vstg + (uint32_t)(kk * 16 * FRS) + vLane + df2 * 32;
                ldsm4t(vh[df2], va);
                ldsm4t(vl[df2], va + FTILE);
            }
#pragma unroll
            for (int nf = 0; nf < 8; nf++)
                mma16816(o[nf], aPh[kk],
                         vh[nf >> 1][(nf & 1) * 2], vh[nf >> 1][(nf & 1) * 2 + 1]);
#pragma unroll
            for (int nf = 0; nf < 8; nf++)
                mma16816(o[nf], aPl[kk],
                         vh[nf >> 1][(nf & 1) * 2], vh[nf >> 1][(nf & 1) * 2 + 1]);
#pragma unroll
            for (int nf = 0; nf < 8; nf++)
                mma16816(o[nf], aPh[kk],
                         vl[nf >> 1][(nf & 1) * 2], vl[nf >> 1][(nf & 1) * 2 + 1]);
        }
        __syncthreads();
    }

    lsA += __shfl_xor_sync(0xffffffffu, lsA, 1);
    lsA += __shfl_xor_sync(0xffffffffu, lsA, 2);
    lsB += __shfl_xor_sync(0xffffffffu, lsB, 1);
    lsB += __shfl_xor_sync(0xffffffffu, lsB, 2);
    float invA = 1.f / lsA, invB = 1.f / lsB;

    int b = bh >> 4, h = bh & 15;
    int rowA = b * 2048 + q0 + w * 16 + (lane >> 2);
    int colBase = h * 64 + (lane & 3) * 2;
#pragma unroll
    for (int nf = 0; nf < 8; nf++) {
        int col = colBase + nf * 8;
        float vA0 = o[nf][0] * invA, vA1 = o[nf][1] * invA;
        float vB0 = o[nf][2] * invB, vB1 = o[nf][3] * invB;
        __nv_bfloat16 hA0 = __float2bfloat16(vA0), hA1 = __float2bfloat16(vA1);
        __nv_bfloat16 hB0 = __float2bfloat16(vB0), hB1 = __float2bfloat16(vB1);
        uint32_t uhA = ((uint32_t)*(uint16_t*)&hA0) | (((uint32_t)*(uint16_t*)&hA1) << 16);
        uint32_t uhB = ((uint32_t)*(uint16_t*)&hB0) | (((uint32_t)*(uint16_t*)&hB1) << 16);
        uint32_t ulA = pack_bf16x2(vA0 - __bfloat162float(hA0), vA1 - __bfloat162float(hA1));
        uint32_t ulB = pack_bf16x2(vB0 - __bfloat162float(hB0), vB1 - __bfloat162float(hB1));
        *(uint32_t*)(g_aoh + (size_t)rowA * 1024 + col) = uhA;
        *(uint32_t*)(g_aol + (size_t)rowA * 1024 + col) = ulA;
        *(uint32_t*)(g_aoh + (size_t)(rowA + 8) * 1024 + col) = uhB;
        *(uint32_t*)(g_aol + (size_t)(rowA + 8) * 1024 + col) = ulB;
    }
}

// ======================= launch =======================
extern "C" void kernel_launch(void* const* d_in, const int* in_sizes, int n_in,
                              void* d_out, int out_size) {
    const float* x = (const float*)d_in[0];
    const float* Wqkv = (const float*)d_in[1];
    const float* Wout = (const float*)d_in[2];
    float* out = (float*)d_out;

    void *p_xhi, *p_xlo, *p_wqh, *p_wql, *p_aoh, *p_aol, *p_woh, *p_wol, *p_v, *p_vh, *p_vl;
    cudaGetSymbolAddress(&p_xhi, g_xhi);
    cudaGetSymbolAddress(&p_xlo, g_xlo);
    cudaGetSymbolAddress(&p_wqh, g_wqh);
    cudaGetSymbolAddress(&p_wql, g_wql);
    cudaGetSymbolAddress(&p_aoh, g_aoh);
    cudaGetSymbolAddress(&p_aol, g_aol);
    cudaGetSymbolAddress(&p_woh, g_woh);
    cudaGetSymbolAddress(&p_wol, g_wol);
    cudaGetSymbolAddress(&p_v,  g_V);
    cudaGetSymbolAddress(&p_vh, g_vh);
    cudaGetSymbolAddress(&p_vl, g_vl);

    cudaFuncSetAttribute(gemm_mma_kernel<0>, cudaFuncAttributeMaxDynamicSharedMemorySize, GEMM_SMEM);
    cudaFuncSetAttribute(gemm_mma_kernel<1>, cudaFuncAttributeMaxDynamicSharedMemorySize, GEMM_SMEM);
    cudaFuncSetAttribute(flash_tc_kernel, cudaFuncAttributeMaxDynamicSharedMemorySize, FLASH_SMEM);

    rope_table_kernel<<<SEQ, 32>>>();

    conv_split_kernel<<<4096, 256>>>(x, (__nv_bfloat16*)p_xhi, (__nv_bfloat16*)p_xlo,
                                     M_ROWS * D_MODEL);
    trans_split_kernel<<<dim3(QKV_N / 32, D_MODEL / 32), dim3(32, 8)>>>(
        Wqkv, (__nv_bfloat16*)p_wqh, (__nv_bfloat16*)p_wql, D_MODEL, QKV_N);

    gemm_mma_kernel<0><<<dim3(QKV_N / 128, M_ROWS / 128), 256, GEMM_SMEM>>>(
        (const __nv_bfloat16*)p_xhi, (const __nv_bfloat16*)p_xlo,
        (const __nv_bfloat16*)p_wqh, (const __nv_bfloat16*)p_wql, nullptr);

    int rope_total = 2 * BATCH * N_HEADS * SEQ * 32;
    rope_split_kernel<<<rope_total / 256, 256>>>();
    conv_split_kernel<<<2048, 256>>>((const float*)p_v,
                                     (__nv_bfloat16*)p_vh, (__nv_bfloat16*)p_vl,
                                     BATCH * N_HEADS * SEQ * HEAD_DIM);

    flash_tc_kernel<<<dim3(16, 64), 256, FLASH_SMEM>>>();

    trans_split_kernel<<<dim3(D_MODEL / 32, D_MODEL / 32), dim3(32, 8)>>>(
        Wout, (__nv_bfloat16*)p_woh, (__nv_bfloat16*)p_wol, D_MODEL, D_MODEL);

    gemm_mma_kernel<1><<<dim3(D_MODEL / 128, M_ROWS / 128), 256, GEMM_SMEM>>>(
        (const __nv_bfloat16*)p_aoh, (const __nv_bfloat16*)p_aol,
        (const __nv_bfloat16*)p_woh, (const __nv_bfloat16*)p_wol, out);
}

// round 6
// speedup vs baseline: 1.0556x; 1.0556x over previous
#include <cuda_runtime.h>
#include <cuda_bf16.h>
#include <math.h>
#include <stdint.h>

#define D_MODEL 1024
#define N_HEADS 16
#define HEAD_DIM 64
#define BATCH 4
#define SEQ 2048
#define M_ROWS (BATCH * SEQ)          // 8192
#define QKV_N (3 * D_MODEL)           // 3072

// ======================= scratch (static device globals) =======================
__device__ __align__(16) float g_Q[BATCH * N_HEADS * SEQ * HEAD_DIM];
__device__ __align__(16) float g_K[BATCH * N_HEADS * SEQ * HEAD_DIM];
__device__ __align__(16) float g_V[BATCH * N_HEADS * SEQ * HEAD_DIM];
__device__ __align__(16) float g_cos[SEQ * 32];
__device__ __align__(16) float g_sin[SEQ * 32];
__device__ __align__(16) __nv_bfloat16 g_xhi[M_ROWS * D_MODEL];
__device__ __align__(16) __nv_bfloat16 g_xlo[M_ROWS * D_MODEL];
__device__ __align__(16) __nv_bfloat16 g_wqh[D_MODEL * QKV_N];
__device__ __align__(16) __nv_bfloat16 g_wql[D_MODEL * QKV_N];
__device__ __align__(16) __nv_bfloat16 g_aoh[M_ROWS * D_MODEL];
__device__ __align__(16) __nv_bfloat16 g_aol[M_ROWS * D_MODEL];
__device__ __align__(16) __nv_bfloat16 g_woh[D_MODEL * D_MODEL];
__device__ __align__(16) __nv_bfloat16 g_wol[D_MODEL * D_MODEL];
__device__ __align__(16) __nv_bfloat16 g_qh[BATCH * N_HEADS * SEQ * HEAD_DIM];
__device__ __align__(16) __nv_bfloat16 g_ql[BATCH * N_HEADS * SEQ * HEAD_DIM];
__device__ __align__(16) __nv_bfloat16 g_kh[BATCH * N_HEADS * SEQ * HEAD_DIM];
__device__ __align__(16) __nv_bfloat16 g_kl[BATCH * N_HEADS * SEQ * HEAD_DIM];
__device__ __align__(16) __nv_bfloat16 g_vh[BATCH * N_HEADS * SEQ * HEAD_DIM];
__device__ __align__(16) __nv_bfloat16 g_vl[BATCH * N_HEADS * SEQ * HEAD_DIM];

// ======================= PTX helpers =======================
__device__ __forceinline__ uint32_t smem_to_u32(const void* smem_ptr) {
    uint32_t addr;
    asm("{ .reg .u64 tmp; cvta.to.shared.u64 tmp, %1; cvt.u32.u64 %0, tmp; }"
        : "=r"(addr) : "l"(smem_ptr));
    return addr;
}
__device__ __forceinline__ void cpa16(uint32_t s, const void* g) {
    asm volatile("cp.async.cg.shared.global [%0], [%1], 16;" :: "r"(s), "l"(g));
}
__device__ __forceinline__ void cpa_commit() {
    asm volatile("cp.async.commit_group;" ::: "memory");
}
__device__ __forceinline__ void ldsm4(uint32_t* r, uint32_t addr) {
    asm volatile("ldmatrix.sync.aligned.m8n8.x4.shared.b16 {%0,%1,%2,%3}, [%4];"
        : "=r"(r[0]), "=r"(r[1]), "=r"(r[2]), "=r"(r[3]) : "r"(addr));
}
__device__ __forceinline__ void ldsm4t(uint32_t* r, uint32_t addr) {
    asm volatile("ldmatrix.sync.aligned.m8n8.x4.trans.shared.b16 {%0,%1,%2,%3}, [%4];"
        : "=r"(r[0]), "=r"(r[1]), "=r"(r[2]), "=r"(r[3]) : "r"(addr));
}
__device__ __forceinline__ void mma16816(float* c, const uint32_t* a, uint32_t b0, uint32_t b1) {
    asm("mma.sync.aligned.m16n8k16.row.col.f32.bf16.bf16.f32 "
        "{%0,%1,%2,%3}, {%4,%5,%6,%7}, {%8,%9}, {%0,%1,%2,%3};"
        : "+f"(c[0]), "+f"(c[1]), "+f"(c[2]), "+f"(c[3])
        : "r"(a[0]), "r"(a[1]), "r"(a[2]), "r"(a[3]), "r"(b0), "r"(b1));
}
__device__ __forceinline__ uint32_t pack_bf16x2(float a, float b) {
    __nv_bfloat162 h = __floats2bfloat162_rn(a, b);
    return *(uint32_t*)&h;
}
__device__ __forceinline__ float ex2f(float x) {
    float r;
    asm("ex2.approx.ftz.f32 %0, %1;" : "=f"(r) : "f"(x));
    return r;
}

// ======================= RoPE table =======================
__global__ void rope_table_kernel() {
    int t = blockIdx.x;
    int i = threadIdx.x;
    double inv = pow(10000.0, -((double)(2 * i)) / 64.0);
    double a = (double)t * inv;
    g_cos[t * 32 + i] = (float)cos(a);
    g_sin[t * 32 + i] = (float)sin(a);
}

// ======================= fp32 -> bf16 hi/lo split =======================
__global__ void conv_split_kernel(const float* __restrict__ in,
                                  __nv_bfloat16* __restrict__ hi,
                                  __nv_bfloat16* __restrict__ lo, int n) {
    int i = blockIdx.x * blockDim.x + threadIdx.x;
    int stride = gridDim.x * blockDim.x;
    for (; i < n; i += stride) {
        float v = in[i];
        __nv_bfloat16 h = __float2bfloat16(v);
        hi[i] = h;
        lo[i] = __float2bfloat16(v - __bfloat162float(h));
    }
}

// ======================= transpose + split =======================
__global__ void trans_split_kernel(const float* __restrict__ W,
                                   __nv_bfloat16* __restrict__ Thi,
                                   __nv_bfloat16* __restrict__ Tlo,
                                   int K, int N) {
    __shared__ float t[32][33];
    int n = blockIdx.x * 32 + threadIdx.x;
    int k0 = blockIdx.y * 32;
#pragma unroll
    for (int r = 0; r < 32; r += 8)
        t[threadIdx.y + r][threadIdx.x] = W[(size_t)(k0 + threadIdx.y + r) * N + n];
    __syncthreads();
    int k = k0 + threadIdx.x;
#pragma unroll
    for (int r = 0; r < 32; r += 8) {
        int n2 = blockIdx.x * 32 + threadIdx.y + r;
        float v = t[threadIdx.x][threadIdx.y + r];
        __nv_bfloat16 h = __float2bfloat16(v);
        Thi[(size_t)n2 * K + k] = h;
        Tlo[(size_t)n2 * K + k] = __float2bfloat16(v - __bfloat162float(h));
    }
}

// ======================= warp-MMA GEMM: 4 warps (2x2), warp tile 64x64 =======================
#define TILE_B   10240                  // 128 rows * 80B padded
#define STG_B    (4 * TILE_B)
#define GEMM_SMEM (2 * STG_B)           // 81920

__device__ __forceinline__ void load_stage(
    uint32_t sb, const __nv_bfloat16* __restrict__ Ahi, const __nv_bfloat16* __restrict__ Alo,
    const __nv_bfloat16* __restrict__ Bhi, const __nv_bfloat16* __restrict__ Blo,
    int m0, int n0, int k0, int tid)
{
    const __nv_bfloat16* gp[4] = { Ahi, Alo, Bhi, Blo };
    int rb[4] = { m0, m0, n0, n0 };
#pragma unroll
    for (int i = 0; i < 16; i++) {
        int ch = tid + i * 128;              // 0..2047
        int tlb = ch >> 9;
        int w2 = ch & 511;
        int row = w2 >> 2, c16 = w2 & 3;
        cpa16(sb + tlb * TILE_B + row * 80 + c16 * 16,
              gp[tlb] + (size_t)(rb[tlb] + row) * 1024 + k0 + c16 * 8);
    }
}

template <int EPI>
__global__ void __launch_bounds__(128, 2) gemm_mma_kernel(
    const __nv_bfloat16* __restrict__ Ahi, const __nv_bfloat16* __restrict__ Alo,
    const __nv_bfloat16* __restrict__ Bhi, const __nv_bfloat16* __restrict__ Blo,
    float* __restrict__ Cout)
{
    extern __shared__ char dsm[];
    uint32_t sb0 = smem_to_u32(dsm);
    int tid = threadIdx.x, lane = tid & 31, wid = tid >> 5;
    int warpM = wid >> 1, warpN = wid & 1;      // 2 x 2
    int m0 = blockIdx.y * 128, n0 = blockIdx.x * 128;

    float c[4][8][4];
#pragma unroll
    for (int i = 0; i < 4; i++)
#pragma unroll
        for (int j = 0; j < 8; j++)
#pragma unroll
            for (int k = 0; k < 4; k++) c[i][j][k] = 0.f;

    uint32_t aRow = (uint32_t)((warpM * 64 + (lane & 15)) * 80 + ((lane >> 4) << 4));
    uint32_t bRow = (uint32_t)((warpN * 64 + ((lane >> 4) << 3) + (lane & 7)) * 80 +
                               (((lane >> 3) & 1) << 4));

    const int NS = 32;
    load_stage(sb0, Ahi, Alo, Bhi, Blo, m0, n0, 0, tid);
    cpa_commit();

    for (int s = 0; s < NS; s++) {
        uint32_t sb = sb0 + (uint32_t)((s & 1) * STG_B);
        if (s + 1 < NS) {
            load_stage(sb0 + (uint32_t)(((s + 1) & 1) * STG_B),
                       Ahi, Alo, Bhi, Blo, m0, n0, (s + 1) * 32, tid);
            cpa_commit();
            asm volatile("cp.async.wait_group 1;" ::: "memory");
        } else {
            asm volatile("cp.async.wait_group 0;" ::: "memory");
        }
        __syncthreads();

#pragma unroll
        for (int k16 = 0; k16 < 2; k16++) {
            uint32_t koff = (uint32_t)(k16 * 32);
            uint32_t ah[4][4], al[4][4], bh[4][4], bl[4][4];
#pragma unroll
            for (int mf = 0; mf < 4; mf++) {
                uint32_t a = sb + aRow + (uint32_t)(mf * 1280) + koff;
                ldsm4(ah[mf], a);
                ldsm4(al[mf], a + TILE_B);
            }
#pragma unroll
            for (int nf2 = 0; nf2 < 4; nf2++) {
                uint32_t b = sb + 2 * TILE_B + bRow + (uint32_t)(nf2 * 1280) + koff;
                ldsm4(bh[nf2], b);
                ldsm4(bl[nf2], b + TILE_B);
            }
#pragma unroll
            for (int mf = 0; mf < 4; mf++)
#pragma unroll
                for (int nf = 0; nf < 8; nf++)
                    mma16816(c[mf][nf], ah[mf],
                             bh[nf >> 1][(nf & 1) * 2], bh[nf >> 1][(nf & 1) * 2 + 1]);
#pragma unroll
            for (int mf = 0; mf < 4; mf++)
#pragma unroll
                for (int nf = 0; nf < 8; nf++)
                    mma16816(c[mf][nf], ah[mf],
                             bl[nf >> 1][(nf & 1) * 2], bl[nf >> 1][(nf & 1) * 2 + 1]);
#pragma unroll
            for (int mf = 0; mf < 4; mf++)
#pragma unroll
                for (int nf = 0; nf < 8; nf++)
                    mma16816(c[mf][nf], al[mf],
                             bh[nf >> 1][(nf & 1) * 2], bh[nf >> 1][(nf & 1) * 2 + 1]);
        }
        __syncthreads();
    }

    int mBase = m0 + warpM * 64 + (lane >> 2);
    int nBase = n0 + warpN * 64 + (lane & 3) * 2;
#pragma unroll
    for (int mf = 0; mf < 4; mf++) {
#pragma unroll
        for (int nf = 0; nf < 8; nf++) {
            int row = mBase + mf * 16;
            int col = nBase + nf * 8;
            if (EPI == 0) {
                int sel = col >> 10, h = (col >> 6) & 15, d = col & 63;
                int b = row >> 11, t = row & 2047;
                float* base = (sel == 0 ? g_Q : (sel == 1 ? g_K : g_V)) +
                              ((size_t)((b * 16 + h) * 2048)) * 64 + d;
                *(float2*)(base + (size_t)t * 64) =
                    make_float2(c[mf][nf][0], c[mf][nf][1]);
                *(float2*)(base + (size_t)(t + 8) * 64) =
                    make_float2(c[mf][nf][2], c[mf][nf][3]);
            } else {
                *(float2*)(Cout + (size_t)row * 1024 + col) =
                    make_float2(c[mf][nf][0], c[mf][nf][1]);
                *(float2*)(Cout + (size_t)(row + 8) * 1024 + col) =
                    make_float2(c[mf][nf][2], c[mf][nf][3]);
            }
        }
    }
}

// ======================= RoPE + bf16 hi/lo split of Q (scaled) and K =======================
__global__ void rope_split_kernel() {
    int idx = blockIdx.x * blockDim.x + threadIdx.x;
    int i = idx & 31;
    int t = (idx >> 5) & 2047;
    int bh = (idx >> 16) & 63;
    int which = idx >> 22;
    size_t base = ((size_t)bh * 2048 + t) * 64;
    float c = g_cos[t * 32 + i];
    float s = g_sin[t * 32 + i];
    const float* X = which ? g_K : g_Q;
    float x1 = X[base + i];
    float x2 = X[base + i + 32];
    float r1 = x1 * c - x2 * s;
    float r2 = x2 * c + x1 * s;
    if (which == 0) {
        const float SC = 0.125f * 1.44269504088896f;
        r1 *= SC; r2 *= SC;
        __nv_bfloat16 h1 = __float2bfloat16(r1);
        __nv_bfloat16 h2 = __float2bfloat16(r2);
        g_qh[base + i] = h1;
        g_qh[base + i + 32] = h2;
        g_ql[base + i] = __float2bfloat16(r1 - __bfloat162float(h1));
        g_ql[base + i + 32] = __float2bfloat16(r2 - __bfloat162float(h2));
    } else {
        __nv_bfloat16 h1 = __float2bfloat16(r1);
        __nv_bfloat16 h2 = __float2bfloat16(r2);
        g_kh[base + i] = h1;
        g_kh[base + i + 32] = h2;
        g_kl[base + i] = __float2bfloat16(r1 - __bfloat162float(h1));
        g_kl[base + i + 32] = __float2bfloat16(r2 - __bfloat162float(h2));
    }
}

// ======================= Tensor-core flash: 4 warps x 32 q-rows =======================
#define FRS 144
#define FTILE (64 * FRS)                 // 9216
#define FQ_B  (128 * FRS)                // 18432
#define FSB_Q 0
#define FSB_KV (2 * FQ_B)                // 36864
#define FSTG_B (4 * FTILE)               // 36864
#define FLASH_SMEM (FSB_KV + 2 * FSTG_B) // 110592

__device__ __forceinline__ void flash_load_q(uint32_t sb, int bh, int q0, int tid) {
#pragma unroll
    for (int i = 0; i < 16; i++) {
        int ch = tid + i * 128;               // 0..2047
        int tl = ch >> 10;
        int r = (ch >> 3) & 127, c16 = ch & 7;
        const __nv_bfloat16* src = (tl ? g_ql : g_qh) +
            ((size_t)bh * SEQ + q0 + r) * 64 + c16 * 8;
        cpa16(sb + FSB_Q + tl * FQ_B + r * FRS + c16 * 16, src);
    }
}
__device__ __forceinline__ void flash_load_kv(uint32_t sb, int bh, int kbase, int stg, int tid) {
    uint32_t d0 = sb + FSB_KV + stg * FSTG_B;
#pragma unroll
    for (int i = 0; i < 16; i++) {
        int ch = tid + i * 128;               // 0..2047
        int tl = ch >> 9;
        int r = (ch >> 3) & 63, c16 = ch & 7;
        const __nv_bfloat16* base = (tl == 0) ? g_kh : (tl == 1) ? g_kl :
                                    (tl == 2) ? g_vh : g_vl;
        cpa16(d0 + tl * FTILE + r * FRS + c16 * 16,
              base + ((size_t)bh * SEQ + kbase + r) * 64 + c16 * 8);
    }
}

__global__ void __launch_bounds__(128, 2) flash_tc_kernel() {
    extern __shared__ char dsm[];
    uint32_t sb = smem_to_u32(dsm);
    int tid = threadIdx.x, lane = tid & 31, w = tid >> 5;   // 4 warps
    int qt = 15 - (int)blockIdx.x;
    int bh = blockIdx.y;
    int q0 = qt * 128;
    int nkt = qt * 2 + 2;

    flash_load_q(sb, bh, q0, tid);
    flash_load_kv(sb, bh, 0, 0, tid);
    cpa_commit();

    uint32_t aQh[2][4][4];        // Q-hi frags resident; Q-lo refetched per kk
    float o[2][8][4];
#pragma unroll
    for (int mf = 0; mf < 2; mf++)
#pragma unroll
        for (int i = 0; i < 8; i++)
#pragma unroll
            for (int j = 0; j < 4; j++) o[mf][i][j] = 0.f;
    float ls[2][2] = {{0.f, 0.f}, {0.f, 0.f}};

    uint32_t qAddr = (uint32_t)((w * 32 + (lane & 15)) * FRS + ((lane >> 4) << 4));
    uint32_t kLane = (uint32_t)((((lane >> 4) << 3) + (lane & 7)) * FRS + (((lane >> 3) & 1) << 4));
    uint32_t vLane = (uint32_t)(((lane & 7) + ((lane >> 3) & 1) * 8) * FRS + ((lane >> 4) << 4));

    for (int kt = 0; kt < nkt; kt++) {
        if (kt + 1 < nkt) {
            flash_load_kv(sb, bh, (kt + 1) * 64, (kt + 1) & 1, tid);
            cpa_commit();
            asm volatile("cp.async.wait_group 1;" ::: "memory");
        } else {
            asm volatile("cp.async.wait_group 0;" ::: "memory");
        }
        __syncthreads();

        if (kt == 0) {
#pragma unroll
            for (int mf = 0; mf < 2; mf++)
#pragma unroll
                for (int kk = 0; kk < 4; kk++)
                    ldsm4(aQh[mf][kk], sb + FSB_Q + qAddr + (uint32_t)(mf * 16 * FRS) + kk * 32);
        }

        uint32_t stg = sb + FSB_KV + (kt & 1) * FSTG_B;
        int kbase = kt * 64;

        // ---- S = Q K^T (3-term, term-major per kk) ----
        float c[2][8][4];
#pragma unroll
        for (int mf = 0; mf < 2; mf++)
#pragma unroll
            for (int i = 0; i < 8; i++)
#pragma unroll
                for (int j = 0; j < 4; j++) c[mf][i][j] = 0.f;

#pragma unroll
        for (int kk = 0; kk < 4; kk++) {
            uint32_t bKh[4][4], bKl[4][4], aQl[2][4];
#pragma unroll
            for (int nf2 = 0; nf2 < 4; nf2++) {
                uint32_t ba = stg + (uint32_t)(nf2 * 16 * FRS) + kLane + kk * 32;
                ldsm4(bKh[nf2], ba);
                ldsm4(bKl[nf2], ba + FTILE);
            }
#pragma unroll
            for (int mf = 0; mf < 2; mf++)
                ldsm4(aQl[mf], sb + FSB_Q + FQ_B + qAddr + (uint32_t)(mf * 16 * FRS) + kk * 32);
#pragma unroll
            for (int mf = 0; mf < 2; mf++)
#pragma unroll
                for (int nf = 0; nf < 8; nf++)
                    mma16816(c[mf][nf], aQh[mf][kk],
                             bKh[nf >> 1][(nf & 1) * 2], bKh[nf >> 1][(nf & 1) * 2 + 1]);
#pragma unroll
            for (int mf = 0; mf < 2; mf++)
#pragma unroll
                for (int nf = 0; nf < 8; nf++)
                    mma16816(c[mf][nf], aQh[mf][kk],
                             bKl[nf >> 1][(nf & 1) * 2], bKl[nf >> 1][(nf & 1) * 2 + 1]);
#pragma unroll
            for (int mf = 0; mf < 2; mf++)
#pragma unroll
                for (int nf = 0; nf < 8; nf++)
                    mma16816(c[mf][nf], aQl[mf],
                             bKh[nf >> 1][(nf & 1) * 2], bKh[nf >> 1][(nf & 1) * 2 + 1]);
        }

        // ---- mask + exp + pack P (hi/lo) ----
        bool needmask = (kbase + 63) > (q0 + w * 32);
        uint32_t aPh[2][4][4], aPl[2][4][4];
#pragma unroll
        for (int mf = 0; mf < 2; mf++) {
            int qrA = q0 + w * 32 + mf * 16 + (lane >> 2);
#pragma unroll
            for (int nf = 0; nf < 8; nf++) {
                if (needmask) {
                    int key0 = kbase + nf * 8 + (lane & 3) * 2;
                    if (key0 > qrA)         c[mf][nf][0] = -100000.f;
                    if (key0 + 1 > qrA)     c[mf][nf][1] = -100000.f;
                    if (key0 > qrA + 8)     c[mf][nf][2] = -100000.f;
                    if (key0 + 1 > qrA + 8) c[mf][nf][3] = -100000.f;
                }
                float p0 = ex2f(c[mf][nf][0]), p1 = ex2f(c[mf][nf][1]);
                float p2 = ex2f(c[mf][nf][2]), p3 = ex2f(c[mf][nf][3]);
                ls[mf][0] += p0 + p1;
                ls[mf][1] += p2 + p3;
                __nv_bfloat16 h0 = __float2bfloat16(p0), h1 = __float2bfloat16(p1);
                __nv_bfloat16 h2 = __float2bfloat16(p2), h3 = __float2bfloat16(p3);
                int kk = nf >> 1, sl = (nf & 1) * 2;
                aPh[mf][kk][sl]     = ((uint32_t)*(uint16_t*)&h0) | (((uint32_t)*(uint16_t*)&h1) << 16);
                aPh[mf][kk][sl + 1] = ((uint32_t)*(uint16_t*)&h2) | (((uint32_t)*(uint16_t*)&h3) << 16);
                aPl[mf][kk][sl]     = pack_bf16x2(p0 - __bfloat162float(h0), p1 - __bfloat162float(h1));
                aPl[mf][kk][sl + 1] = pack_bf16x2(p2 - __bfloat162float(h2), p3 - __bfloat162float(h3));
            }
        }

        // ---- O += P V (3-term, term-major per kk) ----
        uint32_t vstg = stg + 2 * FTILE;
#pragma unroll
        for (int kk = 0; kk < 4; kk++) {
            uint32_t vh[4][4], vl[4][4];
#pragma unroll
            for (int df2 = 0; df2 < 4; df2++) {
                uint32_t va = vstg + (uint32_t)(kk * 16 * FRS) + vLane + df2 * 32;
                ldsm4t(vh[df2], va);
                ldsm4t(vl[df2], va + FTILE);
            }
#pragma unroll
            for (int mf = 0; mf < 2; mf++)
#pragma unroll
                for (int nf = 0; nf < 8; nf++)
                    mma16816(o[mf][nf], aPh[mf][kk],
                             vh[nf >> 1][(nf & 1) * 2], vh[nf >> 1][(nf & 1) * 2 + 1]);
#pragma unroll
            for (int mf = 0; mf < 2; mf++)
#pragma unroll
                for (int nf = 0; nf < 8; nf++)
                    mma16816(o[mf][nf], aPl[mf][kk],
                             vh[nf >> 1][(nf & 1) * 2], vh[nf >> 1][(nf & 1) * 2 + 1]);
#pragma unroll
            for (int mf = 0; mf < 2; mf++)
#pragma unroll
                for (int nf = 0; nf < 8; nf++)
                    mma16816(o[mf][nf], aPh[mf][kk],
                             vl[nf >> 1][(nf & 1) * 2], vl[nf >> 1][(nf & 1) * 2 + 1]);
        }
        __syncthreads();
    }

    int b = bh >> 4, h = bh & 15;
    int colBase = h * 64 + (lane & 3) * 2;
#pragma unroll
    for (int mf = 0; mf < 2; mf++) {
        float lA = ls[mf][0], lB = ls[mf][1];
        lA += __shfl_xor_sync(0xffffffffu, lA, 1);
        lA += __shfl_xor_sync(0xffffffffu, lA, 2);
        lB += __shfl_xor_sync(0xffffffffu, lB, 1);
        lB += __shfl_xor_sync(0xffffffffu, lB, 2);
        float invA = 1.f / lA, invB = 1.f / lB;
        int rowA = b * 2048 + q0 + w * 32 + mf * 16 + (lane >> 2);
#pragma unroll
        for (int nf = 0; nf < 8; nf++) {
            int col = colBase + nf * 8;
            float vA0 = o[mf][nf][0] * invA, vA1 = o[mf][nf][1] * invA;
            float vB0 = o[mf][nf][2] * invB, vB1 = o[mf][nf][3] * invB;
            __nv_bfloat16 hA0 = __float2bfloat16(vA0), hA1 = __float2bfloat16(vA1);
            __nv_bfloat16 hB0 = __float2bfloat16(vB0), hB1 = __float2bfloat16(vB1);
            uint32_t uhA = ((uint32_t)*(uint16_t*)&hA0) | (((uint32_t)*(uint16_t*)&hA1) << 16);
            uint32_t uhB = ((uint32_t)*(uint16_t*)&hB0) | (((uint32_t)*(uint16_t*)&hB1) << 16);
            uint32_t ulA = pack_bf16x2(vA0 - __bfloat162float(hA0), vA1 - __bfloat162float(hA1));
            uint32_t ulB = pack_bf16x2(vB0 - __bfloat162float(hB0), vB1 - __bfloat162float(hB1));
            *(uint32_t*)(g_aoh + (size_t)rowA * 1024 + col) = uhA;
            *(uint32_t*)(g_aol + (size_t)rowA * 1024 + col) = ulA;
            *(uint32_t*)(g_aoh + (size_t)(rowA + 8) * 1024 + col) = uhB;
            *(uint32_t*)(g_aol + (size_t)(rowA + 8) * 1024 + col) = ulB;
        }
    }
}

// ======================= launch =======================
extern "C" void kernel_launch(void* const* d_in, const int* in_sizes, int n_in,
                              void* d_out, int out_size) {
    const float* x = (const float*)d_in[0];
    const float* Wqkv = (const float*)d_in[1];
    const float* Wout = (const float*)d_in[2];
    float* out = (float*)d_out;

    void *p_xhi, *p_xlo, *p_wqh, *p_wql, *p_aoh, *p_aol, *p_woh, *p_wol, *p_v, *p_vh, *p_vl;
    cudaGetSymbolAddress(&p_xhi, g_xhi);
    cudaGetSymbolAddress(&p_xlo, g_xlo);
    cudaGetSymbolAddress(&p_wqh, g_wqh);
    cudaGetSymbolAddress(&p_wql, g_wql);
    cudaGetSymbolAddress(&p_aoh, g_aoh);
    cudaGetSymbolAddress(&p_aol, g_aol);
    cudaGetSymbolAddress(&p_woh, g_woh);
    cudaGetSymbolAddress(&p_wol, g_wol);
    cudaGetSymbolAddress(&p_v,  g_V);
    cudaGetSymbolAddress(&p_vh, g_vh);
    cudaGetSymbolAddress(&p_vl, g_vl);

    cudaFuncSetAttribute(gemm_mma_kernel<0>, cudaFuncAttributeMaxDynamicSharedMemorySize, GEMM_SMEM);
    cudaFuncSetAttribute(gemm_mma_kernel<1>, cudaFuncAttributeMaxDynamicSharedMemorySize, GEMM_SMEM);
    cudaFuncSetAttribute(flash_tc_kernel, cudaFuncAttributeMaxDynamicSharedMemorySize, FLASH_SMEM);

    rope_table_kernel<<<SEQ, 32>>>();

    conv_split_kernel<<<4096, 256>>>(x, (__nv_bfloat16*)p_xhi, (__nv_bfloat16*)p_xlo,
                                     M_ROWS * D_MODEL);
    trans_split_kernel<<<dim3(QKV_N / 32, D_MODEL / 32), dim3(32, 8)>>>(
        Wqkv, (__nv_bfloat16*)p_wqh, (__nv_bfloat16*)p_wql, D_MODEL, QKV_N);

    gemm_mma_kernel<0><<<dim3(QKV_N / 128, M_ROWS / 128), 128, GEMM_SMEM>>>(
        (const __nv_bfloat16*)p_xhi, (const __nv_bfloat16*)p_xlo,
        (const __nv_bfloat16*)p_wqh, (const __nv_bfloat16*)p_wql, nullptr);

    int rope_total = 2 * BATCH * N_HEADS * SEQ * 32;
    rope_split_kernel<<<rope_total / 256, 256>>>();
    conv_split_kernel<<<2048, 256>>>((const float*)p_v,
                                     (__nv_bfloat16*)p_vh, (__nv_bfloat16*)p_vl,
                                     BATCH * N_HEADS * SEQ * HEAD_DIM);

    flash_tc_kernel<<<dim3(16, 64), 128, FLASH_SMEM>>>();

    trans_split_kernel<<<dim3(D_MODEL / 32, D_MODEL / 32), dim3(32, 8)>>>(
        Wout, (__nv_bfloat16*)p_woh, (__nv_bfloat16*)p_wol, D_MODEL, D_MODEL);

    gemm_mma_kernel<1><<<dim3(D_MODEL / 128, M_ROWS / 128), 128, GEMM_SMEM>>>(
        (const __nv_bfloat16*)p_aoh, (const __nv_bfloat16*)p_aol,
        (const __nv_bfloat16*)p_woh, (const __nv_bfloat16*)p_wol, out);
}

// round 7
// speedup vs baseline: 1.6637x; 1.5760x over previous
#include <cuda_runtime.h>
#include <cuda_bf16.h>
#include <cuda_fp16.h>
#include <math.h>
#include <stdint.h>

#define D_MODEL 1024
#define N_HEADS 16
#define HEAD_DIM 64
#define BATCH 4
#define SEQ 2048
#define M_ROWS (BATCH * SEQ)          // 8192
#define QKV_N (3 * D_MODEL)           // 3072

// ======================= scratch (static device globals) =======================
__device__ __align__(16) float g_Q[BATCH * N_HEADS * SEQ * HEAD_DIM];
__device__ __align__(16) float g_K[BATCH * N_HEADS * SEQ * HEAD_DIM];
__device__ __align__(16) float g_V[BATCH * N_HEADS * SEQ * HEAD_DIM];
__device__ __align__(16) float g_cos[SEQ * 32];
__device__ __align__(16) float g_sin[SEQ * 32];
__device__ __align__(16) __half g_xf[M_ROWS * D_MODEL];
__device__ __align__(16) __half g_wqf[D_MODEL * QKV_N];       // transposed [3072][1024]
__device__ __align__(16) __half g_aof[M_ROWS * D_MODEL];
__device__ __align__(16) __half g_wof[D_MODEL * D_MODEL];     // transposed [1024][1024]
// bf16 hi/lo Q,K (3-term scores) ; fp16 V (2-term PV)
__device__ __align__(16) __nv_bfloat16 g_qh[BATCH * N_HEADS * SEQ * HEAD_DIM];
__device__ __align__(16) __nv_bfloat16 g_ql[BATCH * N_HEADS * SEQ * HEAD_DIM];
__device__ __align__(16) __nv_bfloat16 g_kh[BATCH * N_HEADS * SEQ * HEAD_DIM];
__device__ __align__(16) __nv_bfloat16 g_kl[BATCH * N_HEADS * SEQ * HEAD_DIM];
__device__ __align__(16) __half g_vf[BATCH * N_HEADS * SEQ * HEAD_DIM];

// ======================= PTX helpers =======================
__device__ __forceinline__ uint32_t smem_to_u32(const void* smem_ptr) {
    uint32_t addr;
    asm("{ .reg .u64 tmp; cvta.to.shared.u64 tmp, %1; cvt.u32.u64 %0, tmp; }"
        : "=r"(addr) : "l"(smem_ptr));
    return addr;
}
__device__ __forceinline__ void cpa16(uint32_t s, const void* g) {
    asm volatile("cp.async.cg.shared.global [%0], [%1], 16;" :: "r"(s), "l"(g));
}
__device__ __forceinline__ void cpa_commit() {
    asm volatile("cp.async.commit_group;" ::: "memory");
}
__device__ __forceinline__ void ldsm4(uint32_t* r, uint32_t addr) {
    asm volatile("ldmatrix.sync.aligned.m8n8.x4.shared.b16 {%0,%1,%2,%3}, [%4];"
        : "=r"(r[0]), "=r"(r[1]), "=r"(r[2]), "=r"(r[3]) : "r"(addr));
}
__device__ __forceinline__ void ldsm4t(uint32_t* r, uint32_t addr) {
    asm volatile("ldmatrix.sync.aligned.m8n8.x4.trans.shared.b16 {%0,%1,%2,%3}, [%4];"
        : "=r"(r[0]), "=r"(r[1]), "=r"(r[2]), "=r"(r[3]) : "r"(addr));
}
// bf16 mma (scores)
__device__ __forceinline__ void mma16816(float* c, const uint32_t* a, uint32_t b0, uint32_t b1) {
    asm("mma.sync.aligned.m16n8k16.row.col.f32.bf16.bf16.f32 "
        "{%0,%1,%2,%3}, {%4,%5,%6,%7}, {%8,%9}, {%0,%1,%2,%3};"
        : "+f"(c[0]), "+f"(c[1]), "+f"(c[2]), "+f"(c[3])
        : "r"(a[0]), "r"(a[1]), "r"(a[2]), "r"(a[3]), "r"(b0), "r"(b1));
}
// fp16 mma (projections + PV)
__device__ __forceinline__ void mmah(float* c, const uint32_t* a, uint32_t b0, uint32_t b1) {
    asm("mma.sync.aligned.m16n8k16.row.col.f32.f16.f16.f32 "
        "{%0,%1,%2,%3}, {%4,%5,%6,%7}, {%8,%9}, {%0,%1,%2,%3};"
        : "+f"(c[0]), "+f"(c[1]), "+f"(c[2]), "+f"(c[3])
        : "r"(a[0]), "r"(a[1]), "r"(a[2]), "r"(a[3]), "r"(b0), "r"(b1));
}
__device__ __forceinline__ uint32_t pack_h2(float a, float b) {
    __half2 h = __floats2half2_rn(a, b);
    return *(uint32_t*)&h;
}
__device__ __forceinline__ float ex2f(float x) {
    float r;
    asm("ex2.approx.ftz.f32 %0, %1;" : "=f"(r) : "f"(x));
    return r;
}

// ======================= RoPE table =======================
__global__ void rope_table_kernel() {
    int t = blockIdx.x;
    int i = threadIdx.x;
    double inv = pow(10000.0, -((double)(2 * i)) / 64.0);
    double a = (double)t * inv;
    g_cos[t * 32 + i] = (float)cos(a);
    g_sin[t * 32 + i] = (float)sin(a);
}

// ======================= fp32 -> fp16 =======================
__global__ void conv_f16_kernel(const float* __restrict__ in,
                                __half* __restrict__ out, int n) {
    int i = blockIdx.x * blockDim.x + threadIdx.x;
    int stride = gridDim.x * blockDim.x;
    for (; i < n; i += stride) out[i] = __float2half_rn(in[i]);
}

// ======================= transpose fp32 -> fp16 =======================
__global__ void trans_f16_kernel(const float* __restrict__ W,
                                 __half* __restrict__ T, int K, int N) {
    __shared__ float t[32][33];
    int n = blockIdx.x * 32 + threadIdx.x;
    int k0 = blockIdx.y * 32;
#pragma unroll
    for (int r = 0; r < 32; r += 8)
        t[threadIdx.y + r][threadIdx.x] = W[(size_t)(k0 + threadIdx.y + r) * N + n];
    __syncthreads();
    int k = k0 + threadIdx.x;
#pragma unroll
    for (int r = 0; r < 32; r += 8) {
        int n2 = blockIdx.x * 32 + threadIdx.y + r;
        T[(size_t)n2 * K + k] = __float2half_rn(t[threadIdx.x][threadIdx.y + r]);
    }
}

// ======================= fp16 single-term warp-MMA GEMM =======================
// CTA 128x128, 8 warps (2M x 4N), warp tile 64x32, K-stage 32, double-buffered.
#define TILE_B   10240                  // 128 rows * 80B (64B data + 16 pad)
#define STG_B    (2 * TILE_B)           // A, B
#define GEMM_SMEM (2 * STG_B)           // 40960

__device__ __forceinline__ void load_stage(
    uint32_t sb, const __half* __restrict__ Ah, const __half* __restrict__ Bh,
    int m0, int n0, int k0, int tid)
{
    const __half* gp[2] = { Ah, Bh };
    int rb[2] = { m0, n0 };
#pragma unroll
    for (int i = 0; i < 4; i++) {
        int ch = tid + i * 256;              // 0..1023
        int tlb = ch >> 9;
        int w2 = ch & 511;
        int row = w2 >> 2, c16 = w2 & 3;
        cpa16(sb + tlb * TILE_B + row * 80 + c16 * 16,
              gp[tlb] + (size_t)(rb[tlb] + row) * 1024 + k0 + c16 * 8);
    }
}

template <int EPI>
__global__ void __launch_bounds__(256, 2) gemm_mma_kernel(
    const __half* __restrict__ Ah, const __half* __restrict__ Bh,
    float* __restrict__ Cout)
{
    extern __shared__ char dsm[];
    uint32_t sb0 = smem_to_u32(dsm);
    int tid = threadIdx.x, lane = tid & 31, wid = tid >> 5;
    int warpM = wid >> 2, warpN = wid & 3;
    int m0 = blockIdx.y * 128, n0 = blockIdx.x * 128;

    float c[4][4][4];
#pragma unroll
    for (int i = 0; i < 4; i++)
#pragma unroll
        for (int j = 0; j < 4; j++)
#pragma unroll
            for (int k = 0; k < 4; k++) c[i][j][k] = 0.f;

    uint32_t aRow = (uint32_t)((warpM * 64 + (lane & 15)) * 80 + ((lane >> 4) << 4));
    uint32_t bRow = (uint32_t)((warpN * 32 + ((lane >> 4) << 3) + (lane & 7)) * 80 +
                               (((lane >> 3) & 1) << 4));

    const int NS = 32;
    load_stage(sb0, Ah, Bh, m0, n0, 0, tid);
    cpa_commit();

    for (int s = 0; s < NS; s++) {
        uint32_t sb = sb0 + (uint32_t)((s & 1) * STG_B);
        if (s + 1 < NS) {
            load_stage(sb0 + (uint32_t)(((s + 1) & 1) * STG_B),
                       Ah, Bh, m0, n0, (s + 1) * 32, tid);
            cpa_commit();
            asm volatile("cp.async.wait_group 1;" ::: "memory");
        } else {
            asm volatile("cp.async.wait_group 0;" ::: "memory");
        }
        __syncthreads();

#pragma unroll
        for (int k16 = 0; k16 < 2; k16++) {
            uint32_t koff = (uint32_t)(k16 * 32);
            uint32_t af[4][4], bf[2][4];
#pragma unroll
            for (int mf = 0; mf < 4; mf++)
                ldsm4(af[mf], sb + aRow + (uint32_t)(mf * 1280) + koff);
#pragma unroll
            for (int nf2 = 0; nf2 < 2; nf2++)
                ldsm4(bf[nf2], sb + TILE_B + bRow + (uint32_t)(nf2 * 1280) + koff);
#pragma unroll
            for (int mf = 0; mf < 4; mf++)
#pragma unroll
                for (int nf = 0; nf < 4; nf++)
                    mmah(c[mf][nf], af[mf],
                         bf[nf >> 1][(nf & 1) * 2], bf[nf >> 1][(nf & 1) * 2 + 1]);
        }
        __syncthreads();
    }

    int mBase = m0 + warpM * 64 + (lane >> 2);
    int nBase = n0 + warpN * 32 + (lane & 3) * 2;
#pragma unroll
    for (int mf = 0; mf < 4; mf++) {
#pragma unroll
        for (int nf = 0; nf < 4; nf++) {
            int row = mBase + mf * 16;
            int col = nBase + nf * 8;
            if (EPI == 0) {
                int sel = col >> 10, h = (col >> 6) & 15, d = col & 63;
                int b = row >> 11, t = row & 2047;
                float* base = (sel == 0 ? g_Q : (sel == 1 ? g_K : g_V)) +
                              ((size_t)((b * 16 + h) * 2048)) * 64 + d;
                *(float2*)(base + (size_t)t * 64) =
                    make_float2(c[mf][nf][0], c[mf][nf][1]);
                *(float2*)(base + (size_t)(t + 8) * 64) =
                    make_float2(c[mf][nf][2], c[mf][nf][3]);
            } else {
                *(float2*)(Cout + (size_t)row * 1024 + col) =
                    make_float2(c[mf][nf][0], c[mf][nf][1]);
                *(float2*)(Cout + (size_t)(row + 8) * 1024 + col) =
                    make_float2(c[mf][nf][2], c[mf][nf][3]);
            }
        }
    }
}

// ======================= RoPE + bf16 hi/lo split of Q (scaled) and K =======================
__global__ void rope_split_kernel() {
    int idx = blockIdx.x * blockDim.x + threadIdx.x;
    int i = idx & 31;
    int t = (idx >> 5) & 2047;
    int bh = (idx >> 16) & 63;
    int which = idx >> 22;
    size_t base = ((size_t)bh * 2048 + t) * 64;
    float c = g_cos[t * 32 + i];
    float s = g_sin[t * 32 + i];
    const float* X = which ? g_K : g_Q;
    float x1 = X[base + i];
    float x2 = X[base + i + 32];
    float r1 = x1 * c - x2 * s;
    float r2 = x2 * c + x1 * s;
    if (which == 0) {
        const float SC = 0.125f * 1.44269504088896f;
        r1 *= SC; r2 *= SC;
        __nv_bfloat16 h1 = __float2bfloat16(r1);
        __nv_bfloat16 h2 = __float2bfloat16(r2);
        g_qh[base + i] = h1;
        g_qh[base + i + 32] = h2;
        g_ql[base + i] = __float2bfloat16(r1 - __bfloat162float(h1));
        g_ql[base + i + 32] = __float2bfloat16(r2 - __bfloat162float(h2));
    } else {
        __nv_bfloat16 h1 = __float2bfloat16(r1);
        __nv_bfloat16 h2 = __float2bfloat16(r2);
        g_kh[base + i] = h1;
        g_kh[base + i + 32] = h2;
        g_kl[base + i] = __float2bfloat16(r1 - __bfloat162float(h1));
        g_kl[base + i + 32] = __float2bfloat16(r2 - __bfloat162float(h2));
    }
}

// ======================= Tensor-core flash: 4 warps x 32 q-rows =======================
// S = QK^T : 3-term bf16.  O = PV : 2-term fp16 (P split hi/lo, V single).
#define FRS 144
#define FTILE (64 * FRS)                 // 9216
#define FQ_B  (128 * FRS)                // 18432
#define FSB_Q 0
#define FSB_KV (2 * FQ_B)                // 36864
#define FSTG_B (3 * FTILE)               // Khi, Klo, Vf = 27648
#define FLASH_SMEM (FSB_KV + 2 * FSTG_B) // 92160

__device__ __forceinline__ void flash_load_q(uint32_t sb, int bh, int q0, int tid) {
#pragma unroll
    for (int i = 0; i < 16; i++) {
        int ch = tid + i * 128;               // 0..2047
        int tl = ch >> 10;
        int r = (ch >> 3) & 127, c16 = ch & 7;
        const __nv_bfloat16* src = (tl ? g_ql : g_qh) +
            ((size_t)bh * SEQ + q0 + r) * 64 + c16 * 8;
        cpa16(sb + FSB_Q + tl * FQ_B + r * FRS + c16 * 16, src);
    }
}
__device__ __forceinline__ void flash_load_kv(uint32_t sb, int bh, int kbase, int stg, int tid) {
    uint32_t d0 = sb + FSB_KV + stg * FSTG_B;
#pragma unroll
    for (int i = 0; i < 12; i++) {
        int ch = tid + i * 128;               // 0..1535
        int tl = ch >> 9;                     // 0 Khi, 1 Klo, 2 Vf
        int r = (ch >> 3) & 63, c16 = ch & 7;
        const void* src;
        if (tl == 0)      src = g_kh + ((size_t)bh * SEQ + kbase + r) * 64 + c16 * 8;
        else if (tl == 1) src = g_kl + ((size_t)bh * SEQ + kbase + r) * 64 + c16 * 8;
        else              src = g_vf + ((size_t)bh * SEQ + kbase + r) * 64 + c16 * 8;
        cpa16(d0 + tl * FTILE + r * FRS + c16 * 16, src);
    }
}

__global__ void __launch_bounds__(128, 2) flash_tc_kernel() {
    extern __shared__ char dsm[];
    uint32_t sb = smem_to_u32(dsm);
    int tid = threadIdx.x, lane = tid & 31, w = tid >> 5;
    int qt = 15 - (int)blockIdx.x;
    int bh = blockIdx.y;
    int q0 = qt * 128;
    int nkt = qt * 2 + 2;

    flash_load_q(sb, bh, q0, tid);
    flash_load_kv(sb, bh, 0, 0, tid);
    cpa_commit();

    uint32_t aQh[2][4][4];
    float o[2][8][4];
#pragma unroll
    for (int mf = 0; mf < 2; mf++)
#pragma unroll
        for (int i = 0; i < 8; i++)
#pragma unroll
            for (int j = 0; j < 4; j++) o[mf][i][j] = 0.f;
    float ls[2][2] = {{0.f, 0.f}, {0.f, 0.f}};

    uint32_t qAddr = (uint32_t)((w * 32 + (lane & 15)) * FRS + ((lane >> 4) << 4));
    uint32_t kLane = (uint32_t)((((lane >> 4) << 3) + (lane & 7)) * FRS + (((lane >> 3) & 1) << 4));
    uint32_t vLane = (uint32_t)(((lane & 7) + ((lane >> 3) & 1) * 8) * FRS + ((lane >> 4) << 4));

    for (int kt = 0; kt < nkt; kt++) {
        if (kt + 1 < nkt) {
            flash_load_kv(sb, bh, (kt + 1) * 64, (kt + 1) & 1, tid);
            cpa_commit();
            asm volatile("cp.async.wait_group 1;" ::: "memory");
        } else {
            asm volatile("cp.async.wait_group 0;" ::: "memory");
        }
        __syncthreads();

        if (kt == 0) {
#pragma unroll
            for (int mf = 0; mf < 2; mf++)
#pragma unroll
                for (int kk = 0; kk < 4; kk++)
                    ldsm4(aQh[mf][kk], sb + FSB_Q + qAddr + (uint32_t)(mf * 16 * FRS) + kk * 32);
        }

        uint32_t stg = sb + FSB_KV + (kt & 1) * FSTG_B;
        int kbase = kt * 64;

        // ---- S = Q K^T (3-term bf16, term-major per kk) ----
        float c[2][8][4];
#pragma unroll
        for (int mf = 0; mf < 2; mf++)
#pragma unroll
            for (int i = 0; i < 8; i++)
#pragma unroll
                for (int j = 0; j < 4; j++) c[mf][i][j] = 0.f;

#pragma unroll
        for (int kk = 0; kk < 4; kk++) {
            uint32_t bKh[4][4], bKl[4][4], aQl[2][4];
#pragma unroll
            for (int nf2 = 0; nf2 < 4; nf2++) {
                uint32_t ba = stg + (uint32_t)(nf2 * 16 * FRS) + kLane + kk * 32;
                ldsm4(bKh[nf2], ba);
                ldsm4(bKl[nf2], ba + FTILE);
            }
#pragma unroll
            for (int mf = 0; mf < 2; mf++)
                ldsm4(aQl[mf], sb + FSB_Q + FQ_B + qAddr + (uint32_t)(mf * 16 * FRS) + kk * 32);
#pragma unroll
            for (int mf = 0; mf < 2; mf++)
#pragma unroll
                for (int nf = 0; nf < 8; nf++)
                    mma16816(c[mf][nf], aQh[mf][kk],
                             bKh[nf >> 1][(nf & 1) * 2], bKh[nf >> 1][(nf & 1) * 2 + 1]);
#pragma unroll
            for (int mf = 0; mf < 2; mf++)
#pragma unroll
                for (int nf = 0; nf < 8; nf++)
                    mma16816(c[mf][nf], aQh[mf][kk],
                             bKl[nf >> 1][(nf & 1) * 2], bKl[nf >> 1][(nf & 1) * 2 + 1]);
#pragma unroll
            for (int mf = 0; mf < 2; mf++)
#pragma unroll
                for (int nf = 0; nf < 8; nf++)
                    mma16816(c[mf][nf], aQl[mf],
                             bKh[nf >> 1][(nf & 1) * 2], bKh[nf >> 1][(nf & 1) * 2 + 1]);
        }

        // ---- mask + exp + pack P (fp16 hi/lo) ----
        bool needmask = (kbase + 63) > (q0 + w * 32);
        uint32_t aPh[2][4][4], aPl[2][4][4];
#pragma unroll
        for (int mf = 0; mf < 2; mf++) {
            int qrA = q0 + w * 32 + mf * 16 + (lane >> 2);
#pragma unroll
            for (int nf = 0; nf < 8; nf++) {
                if (needmask) {
                    int key0 = kbase + nf * 8 + (lane & 3) * 2;
                    if (key0 > qrA)         c[mf][nf][0] = -100000.f;
                    if (key0 + 1 > qrA)     c[mf][nf][1] = -100000.f;
                    if (key0 > qrA + 8)     c[mf][nf][2] = -100000.f;
                    if (key0 + 1 > qrA + 8) c[mf][nf][3] = -100000.f;
                }
                float p0 = ex2f(c[mf][nf][0]), p1 = ex2f(c[mf][nf][1]);
                float p2 = ex2f(c[mf][nf][2]), p3 = ex2f(c[mf][nf][3]);
                ls[mf][0] += p0 + p1;
                ls[mf][1] += p2 + p3;
                __half h0 = __float2half_rn(p0), h1 = __float2half_rn(p1);
                __half h2 = __float2half_rn(p2), h3 = __float2half_rn(p3);
                int kk = nf >> 1, sl = (nf & 1) * 2;
                aPh[mf][kk][sl]     = ((uint32_t)*(uint16_t*)&h0) | (((uint32_t)*(uint16_t*)&h1) << 16);
                aPh[mf][kk][sl + 1] = ((uint32_t)*(uint16_t*)&h2) | (((uint32_t)*(uint16_t*)&h3) << 16);
                aPl[mf][kk][sl]     = pack_h2(p0 - __half2float(h0), p1 - __half2float(h1));
                aPl[mf][kk][sl + 1] = pack_h2(p2 - __half2float(h2), p3 - __half2float(h3));
            }
        }

        // ---- O += P V (2-term fp16, term-major per kk) ----
        uint32_t vstg = stg + 2 * FTILE;
#pragma unroll
        for (int kk = 0; kk < 4; kk++) {
            uint32_t vf[4][4];
#pragma unroll
            for (int df2 = 0; df2 < 4; df2++)
                ldsm4t(vf[df2], vstg + (uint32_t)(kk * 16 * FRS) + vLane + df2 * 32);
#pragma unroll
            for (int mf = 0; mf < 2; mf++)
#pragma unroll
                for (int nf = 0; nf < 8; nf++)
                    mmah(o[mf][nf], aPh[mf][kk],
                         vf[nf >> 1][(nf & 1) * 2], vf[nf >> 1][(nf & 1) * 2 + 1]);
#pragma unroll
            for (int mf = 0; mf < 2; mf++)
#pragma unroll
                for (int nf = 0; nf < 8; nf++)
                    mmah(o[mf][nf], aPl[mf][kk],
                         vf[nf >> 1][(nf & 1) * 2], vf[nf >> 1][(nf & 1) * 2 + 1]);
        }
        __syncthreads();
    }

    int b = bh >> 4, h = bh & 15;
    int colBase = h * 64 + (lane & 3) * 2;
#pragma unroll
    for (int mf = 0; mf < 2; mf++) {
        float lA = ls[mf][0], lB = ls[mf][1];
        lA += __shfl_xor_sync(0xffffffffu, lA, 1);
        lA += __shfl_xor_sync(0xffffffffu, lA, 2);
        lB += __shfl_xor_sync(0xffffffffu, lB, 1);
        lB += __shfl_xor_sync(0xffffffffu, lB, 2);
        float invA = 1.f / lA, invB = 1.f / lB;
        int rowA = b * 2048 + q0 + w * 32 + mf * 16 + (lane >> 2);
#pragma unroll
        for (int nf = 0; nf < 8; nf++) {
            int col = colBase + nf * 8;
            *(uint32_t*)(g_aof + (size_t)rowA * 1024 + col) =
                pack_h2(o[mf][nf][0] * invA, o[mf][nf][1] * invA);
            *(uint32_t*)(g_aof + (size_t)(rowA + 8) * 1024 + col) =
                pack_h2(o[mf][nf][2] * invB, o[mf][nf][3] * invB);
        }
    }
}

// ======================= V fp32 -> fp16 =======================
__global__ void conv_v_kernel() {
    int i = blockIdx.x * blockDim.x + threadIdx.x;
    g_vf[i] = __float2half_rn(g_V[i]);
}

// ======================= launch =======================
extern "C" void kernel_launch(void* const* d_in, const int* in_sizes, int n_in,
                              void* d_out, int out_size) {
    const float* x = (const float*)d_in[0];
    const float* Wqkv = (const float*)d_in[1];
    const float* Wout = (const float*)d_in[2];
    float* out = (float*)d_out;

    void *p_xf, *p_wqf, *p_aof, *p_wof;
    cudaGetSymbolAddress(&p_xf,  g_xf);
    cudaGetSymbolAddress(&p_wqf, g_wqf);
    cudaGetSymbolAddress(&p_aof, g_aof);
    cudaGetSymbolAddress(&p_wof, g_wof);

    cudaFuncSetAttribute(gemm_mma_kernel<0>, cudaFuncAttributeMaxDynamicSharedMemorySize, GEMM_SMEM);
    cudaFuncSetAttribute(gemm_mma_kernel<1>, cudaFuncAttributeMaxDynamicSharedMemorySize, GEMM_SMEM);
    cudaFuncSetAttribute(flash_tc_kernel, cudaFuncAttributeMaxDynamicSharedMemorySize, FLASH_SMEM);

    rope_table_kernel<<<SEQ, 32>>>();

    conv_f16_kernel<<<4096, 256>>>(x, (__half*)p_xf, M_ROWS * D_MODEL);
    trans_f16_kernel<<<dim3(QKV_N / 32, D_MODEL / 32), dim3(32, 8)>>>(
        Wqkv, (__half*)p_wqf, D_MODEL, QKV_N);

    gemm_mma_kernel<0><<<dim3(QKV_N / 128, M_ROWS / 128), 256, GEMM_SMEM>>>(
        (const __half*)p_xf, (const __half*)p_wqf, nullptr);

    int rope_total = 2 * BATCH * N_HEADS * SEQ * 32;
    rope_split_kernel<<<rope_total / 256, 256>>>();
    conv_v_kernel<<<BATCH * N_HEADS * SEQ * HEAD_DIM / 256, 256>>>();

    flash_tc_kernel<<<dim3(16, 64), 128, FLASH_SMEM>>>();

    trans_f16_kernel<<<dim3(D_MODEL / 32, D_MODEL / 32), dim3(32, 8)>>>(
        Wout, (__half*)p_wof, D_MODEL, D_MODEL);

    gemm_mma_kernel<1><<<dim3(D_MODEL / 128, M_ROWS / 128), 256, GEMM_SMEM>>>(
        (const __half*)p_aof, (const __half*)p_wof, out);
}

// round 8
// speedup vs baseline: 1.8336x; 1.1021x over previous
#include <cuda_runtime.h>
#include <cuda_bf16.h>
#include <cuda_fp16.h>
#include <math.h>
#include <stdint.h>

#define D_MODEL 1024
#define N_HEADS 16
#define HEAD_DIM 64
#define BATCH 4
#define SEQ 2048
#define M_ROWS (BATCH * SEQ)          // 8192
#define QKV_N (3 * D_MODEL)           // 3072

// ======================= scratch (static device globals) =======================
__device__ __align__(16) float g_Q[BATCH * N_HEADS * SEQ * HEAD_DIM];
__device__ __align__(16) float g_K[BATCH * N_HEADS * SEQ * HEAD_DIM];
__device__ __align__(16) float g_cos[SEQ * 32];
__device__ __align__(16) float g_sin[SEQ * 32];
__device__ __align__(16) __half g_xf[M_ROWS * D_MODEL];
__device__ __align__(16) __half g_wqf[D_MODEL * QKV_N];       // transposed [3072][1024]
__device__ __align__(16) __half g_aof[M_ROWS * D_MODEL];
__device__ __align__(16) __half g_wof[D_MODEL * D_MODEL];     // transposed [1024][1024]
__device__ __align__(16) __nv_bfloat16 g_qh[BATCH * N_HEADS * SEQ * HEAD_DIM];
__device__ __align__(16) __nv_bfloat16 g_ql[BATCH * N_HEADS * SEQ * HEAD_DIM];
__device__ __align__(16) __nv_bfloat16 g_kh[BATCH * N_HEADS * SEQ * HEAD_DIM];
__device__ __align__(16) __nv_bfloat16 g_kl[BATCH * N_HEADS * SEQ * HEAD_DIM];
__device__ __align__(16) __half g_vf[BATCH * N_HEADS * SEQ * HEAD_DIM];

// ======================= PTX helpers =======================
__device__ __forceinline__ uint32_t smem_to_u32(const void* smem_ptr) {
    uint32_t addr;
    asm("{ .reg .u64 tmp; cvta.to.shared.u64 tmp, %1; cvt.u32.u64 %0, tmp; }"
        : "=r"(addr) : "l"(smem_ptr));
    return addr;
}
__device__ __forceinline__ void cpa16(uint32_t s, const void* g) {
    asm volatile("cp.async.cg.shared.global [%0], [%1], 16;" :: "r"(s), "l"(g));
}
__device__ __forceinline__ void cpa_commit() {
    asm volatile("cp.async.commit_group;" ::: "memory");
}
__device__ __forceinline__ void ldsm4(uint32_t* r, uint32_t addr) {
    asm volatile("ldmatrix.sync.aligned.m8n8.x4.shared.b16 {%0,%1,%2,%3}, [%4];"
        : "=r"(r[0]), "=r"(r[1]), "=r"(r[2]), "=r"(r[3]) : "r"(addr));
}
__device__ __forceinline__ void ldsm4t(uint32_t* r, uint32_t addr) {
    asm volatile("ldmatrix.sync.aligned.m8n8.x4.trans.shared.b16 {%0,%1,%2,%3}, [%4];"
        : "=r"(r[0]), "=r"(r[1]), "=r"(r[2]), "=r"(r[3]) : "r"(addr));
}
__device__ __forceinline__ void mma16816(float* c, const uint32_t* a, uint32_t b0, uint32_t b1) {
    asm("mma.sync.aligned.m16n8k16.row.col.f32.bf16.bf16.f32 "
        "{%0,%1,%2,%3}, {%4,%5,%6,%7}, {%8,%9}, {%0,%1,%2,%3};"
        : "+f"(c[0]), "+f"(c[1]), "+f"(c[2]), "+f"(c[3])
        : "r"(a[0]), "r"(a[1]), "r"(a[2]), "r"(a[3]), "r"(b0), "r"(b1));
}
__device__ __forceinline__ void mmah(float* c, const uint32_t* a, uint32_t b0, uint32_t b1) {
    asm("mma.sync.aligned.m16n8k16.row.col.f32.f16.f16.f32 "
        "{%0,%1,%2,%3}, {%4,%5,%6,%7}, {%8,%9}, {%0,%1,%2,%3};"
        : "+f"(c[0]), "+f"(c[1]), "+f"(c[2]), "+f"(c[3])
        : "r"(a[0]), "r"(a[1]), "r"(a[2]), "r"(a[3]), "r"(b0), "r"(b1));
}
__device__ __forceinline__ uint32_t pack_h2(float a, float b) {
    __half2 h = __floats2half2_rn(a, b);
    return *(uint32_t*)&h;
}
__device__ __forceinline__ float ex2f(float x) {
    float r;
    asm("ex2.approx.ftz.f32 %0, %1;" : "=f"(r) : "f"(x));
    return r;
}

// ======================= RoPE table =======================
__global__ void rope_table_kernel() {
    int t = blockIdx.x;
    int i = threadIdx.x;
    double inv = pow(10000.0, -((double)(2 * i)) / 64.0);
    double a = (double)t * inv;
    g_cos[t * 32 + i] = (float)cos(a);
    g_sin[t * 32 + i] = (float)sin(a);
}

// ======================= fp32 -> fp16 =======================
__global__ void conv_f16_kernel(const float* __restrict__ in,
                                __half* __restrict__ out, int n) {
    int i = blockIdx.x * blockDim.x + threadIdx.x;
    int stride = gridDim.x * blockDim.x;
    for (; i < n; i += stride) out[i] = __float2half_rn(in[i]);
}

// ======================= transpose fp32 -> fp16 =======================
__global__ void trans_f16_kernel(const float* __restrict__ W,
                                 __half* __restrict__ T, int K, int N) {
    __shared__ float t[32][33];
    int n = blockIdx.x * 32 + threadIdx.x;
    int k0 = blockIdx.y * 32;
#pragma unroll
    for (int r = 0; r < 32; r += 8)
        t[threadIdx.y + r][threadIdx.x] = W[(size_t)(k0 + threadIdx.y + r) * N + n];
    __syncthreads();
    int k = k0 + threadIdx.x;
#pragma unroll
    for (int r = 0; r < 32; r += 8) {
        int n2 = blockIdx.x * 32 + threadIdx.y + r;
        T[(size_t)n2 * K + k] = __float2half_rn(t[threadIdx.x][threadIdx.y + r]);
    }
}

// ======================= fp16 warp-MMA GEMM: 4 warps (2x2), warp tile 64x64 =======================
#define TILE_B   10240                  // 128 rows * 80B (64B data + 16 pad)
#define STG_B    (2 * TILE_B)           // A, B
#define GEMM_SMEM (2 * STG_B)           // 40960

__device__ __forceinline__ void load_stage(
    uint32_t sb, const __half* __restrict__ Ah, const __half* __restrict__ Bh,
    int m0, int n0, int k0, int tid)
{
    const __half* gp[2] = { Ah, Bh };
    int rb[2] = { m0, n0 };
#pragma unroll
    for (int i = 0; i < 8; i++) {
        int ch = tid + i * 128;              // 0..1023
        int tlb = ch >> 9;
        int w2 = ch & 511;
        int row = w2 >> 2, c16 = w2 & 3;
        cpa16(sb + tlb * TILE_B + row * 80 + c16 * 16,
              gp[tlb] + (size_t)(rb[tlb] + row) * 1024 + k0 + c16 * 8);
    }
}

template <int EPI>  // 0: scatter Q/K fp32 + V fp16, 1: plain fp32 store
__global__ void __launch_bounds__(128, 2) gemm_mma_kernel(
    const __half* __restrict__ Ah, const __half* __restrict__ Bh,
    float* __restrict__ Cout)
{
    extern __shared__ char dsm[];
    uint32_t sb0 = smem_to_u32(dsm);
    int tid = threadIdx.x, lane = tid & 31, wid = tid >> 5;
    int warpM = wid >> 1, warpN = wid & 1;      // 2 x 2
    int m0 = blockIdx.y * 128, n0 = blockIdx.x * 128;

    float c[4][8][4];
#pragma unroll
    for (int i = 0; i < 4; i++)
#pragma unroll
        for (int j = 0; j < 8; j++)
#pragma unroll
            for (int k = 0; k < 4; k++) c[i][j][k] = 0.f;

    uint32_t aRow = (uint32_t)((warpM * 64 + (lane & 15)) * 80 + ((lane >> 4) << 4));
    uint32_t bRow = (uint32_t)((warpN * 64 + ((lane >> 4) << 3) + (lane & 7)) * 80 +
                               (((lane >> 3) & 1) << 4));

    const int NS = 32;
    load_stage(sb0, Ah, Bh, m0, n0, 0, tid);
    cpa_commit();

    for (int s = 0; s < NS; s++) {
        uint32_t sb = sb0 + (uint32_t)((s & 1) * STG_B);
        if (s + 1 < NS) {
            load_stage(sb0 + (uint32_t)(((s + 1) & 1) * STG_B),
                       Ah, Bh, m0, n0, (s + 1) * 32, tid);
            cpa_commit();
            asm volatile("cp.async.wait_group 1;" ::: "memory");
        } else {
            asm volatile("cp.async.wait_group 0;" ::: "memory");
        }
        __syncthreads();

#pragma unroll
        for (int k16 = 0; k16 < 2; k16++) {
            uint32_t koff = (uint32_t)(k16 * 32);
            uint32_t af[4][4], bf[4][4];
#pragma unroll
            for (int mf = 0; mf < 4; mf++)
                ldsm4(af[mf], sb + aRow + (uint32_t)(mf * 1280) + koff);
#pragma unroll
            for (int nf2 = 0; nf2 < 4; nf2++)
                ldsm4(bf[nf2], sb + TILE_B + bRow + (uint32_t)(nf2 * 1280) + koff);
#pragma unroll
            for (int mf = 0; mf < 4; mf++)
#pragma unroll
                for (int nf = 0; nf < 8; nf++)
                    mmah(c[mf][nf], af[mf],
                         bf[nf >> 1][(nf & 1) * 2], bf[nf >> 1][(nf & 1) * 2 + 1]);
        }
        __syncthreads();
    }

    int mBase = m0 + warpM * 64 + (lane >> 2);
    int nBase = n0 + warpN * 64 + (lane & 3) * 2;
#pragma unroll
    for (int mf = 0; mf < 4; mf++) {
#pragma unroll
        for (int nf = 0; nf < 8; nf++) {
            int row = mBase + mf * 16;
            int col = nBase + nf * 8;
            if (EPI == 0) {
                int sel = col >> 10, h = (col >> 6) & 15, d = col & 63;
                int b = row >> 11, t = row & 2047;
                size_t off = ((size_t)((b * 16 + h) * 2048)) * 64 + d;
                if (sel == 2) {
                    *(uint32_t*)(g_vf + off + (size_t)t * 64) =
                        pack_h2(c[mf][nf][0], c[mf][nf][1]);
                    *(uint32_t*)(g_vf + off + (size_t)(t + 8) * 64) =
                        pack_h2(c[mf][nf][2], c[mf][nf][3]);
                } else {
                    float* base = (sel == 0 ? g_Q : g_K) + off;
                    *(float2*)(base + (size_t)t * 64) =
                        make_float2(c[mf][nf][0], c[mf][nf][1]);
                    *(float2*)(base + (size_t)(t + 8) * 64) =
                        make_float2(c[mf][nf][2], c[mf][nf][3]);
                }
            } else {
                *(float2*)(Cout + (size_t)row * 1024 + col) =
                    make_float2(c[mf][nf][0], c[mf][nf][1]);
                *(float2*)(Cout + (size_t)(row + 8) * 1024 + col) =
                    make_float2(c[mf][nf][2], c[mf][nf][3]);
            }
        }
    }
}

// ======================= RoPE + bf16 hi/lo split of Q (scaled) and K =======================
__global__ void rope_split_kernel() {
    int idx = blockIdx.x * blockDim.x + threadIdx.x;
    int i = idx & 31;
    int t = (idx >> 5) & 2047;
    int bh = (idx >> 16) & 63;
    int which = idx >> 22;
    size_t base = ((size_t)bh * 2048 + t) * 64;
    float c = g_cos[t * 32 + i];
    float s = g_sin[t * 32 + i];
    const float* X = which ? g_K : g_Q;
    float x1 = X[base + i];
    float x2 = X[base + i + 32];
    float r1 = x1 * c - x2 * s;
    float r2 = x2 * c + x1 * s;
    if (which == 0) {
        const float SC = 0.125f * 1.44269504088896f;
        r1 *= SC; r2 *= SC;
        __nv_bfloat16 h1 = __float2bfloat16(r1);
        __nv_bfloat16 h2 = __float2bfloat16(r2);
        g_qh[base + i] = h1;
        g_qh[base + i + 32] = h2;
        g_ql[base + i] = __float2bfloat16(r1 - __bfloat162float(h1));
        g_ql[base + i + 32] = __float2bfloat16(r2 - __bfloat162float(h2));
    } else {
        __nv_bfloat16 h1 = __float2bfloat16(r1);
        __nv_bfloat16 h2 = __float2bfloat16(r2);
        g_kh[base + i] = h1;
        g_kh[base + i + 32] = h2;
        g_kl[base + i] = __float2bfloat16(r1 - __bfloat162float(h1));
        g_kl[base + i + 32] = __float2bfloat16(r2 - __bfloat162float(h2));
    }
}

// ======================= Tensor-core flash: 4 warps x 32 q-rows =======================
// S = QK^T : 3-term bf16.  O = PV : 2-term fp16 (P split hi/lo, V single).
#define FRS 144
#define FTILE (64 * FRS)                 // 9216
#define FQ_B  (128 * FRS)                // 18432
#define FSB_Q 0
#define FSB_KV (2 * FQ_B)                // 36864
#define FSTG_B (3 * FTILE)               // Khi, Klo, Vf = 27648
#define FLASH_SMEM (FSB_KV + 2 * FSTG_B) // 92160

__device__ __forceinline__ void flash_load_q(uint32_t sb, int bh, int q0, int tid) {
#pragma unroll
    for (int i = 0; i < 16; i++) {
        int ch = tid + i * 128;               // 0..2047
        int tl = ch >> 10;
        int r = (ch >> 3) & 127, c16 = ch & 7;
        const __nv_bfloat16* src = (tl ? g_ql : g_qh) +
            ((size_t)bh * SEQ + q0 + r) * 64 + c16 * 8;
        cpa16(sb + FSB_Q + tl * FQ_B + r * FRS + c16 * 16, src);
    }
}
__device__ __forceinline__ void flash_load_kv(uint32_t sb, int bh, int kbase, int stg, int tid) {
    uint32_t d0 = sb + FSB_KV + stg * FSTG_B;
#pragma unroll
    for (int i = 0; i < 12; i++) {
        int ch = tid + i * 128;               // 0..1535
        int tl = ch >> 9;                     // 0 Khi, 1 Klo, 2 Vf
        int r = (ch >> 3) & 63, c16 = ch & 7;
        const void* src;
        if (tl == 0)      src = g_kh + ((size_t)bh * SEQ + kbase + r) * 64 + c16 * 8;
        else if (tl == 1) src = g_kl + ((size_t)bh * SEQ + kbase + r) * 64 + c16 * 8;
        else              src = g_vf + ((size_t)bh * SEQ + kbase + r) * 64 + c16 * 8;
        cpa16(d0 + tl * FTILE + r * FRS + c16 * 16, src);
    }
}

__global__ void __launch_bounds__(128, 2) flash_tc_kernel() {
    extern __shared__ char dsm[];
    uint32_t sb = smem_to_u32(dsm);
    int tid = threadIdx.x, lane = tid & 31, w = tid >> 5;
    int qt = 15 - (int)blockIdx.x;
    int bh = blockIdx.y;
    int q0 = qt * 128;
    int nkt = qt * 2 + 2;

    flash_load_q(sb, bh, q0, tid);
    flash_load_kv(sb, bh, 0, 0, tid);
    cpa_commit();

    uint32_t aQh[2][4][4], aQl[2][4][4];      // both resident
    float o[2][8][4];
#pragma unroll
    for (int mf = 0; mf < 2; mf++)
#pragma unroll
        for (int i = 0; i < 8; i++)
#pragma unroll
            for (int j = 0; j < 4; j++) o[mf][i][j] = 0.f;
    float ls[2][2] = {{0.f, 0.f}, {0.f, 0.f}};

    uint32_t qAddr = (uint32_t)((w * 32 + (lane & 15)) * FRS + ((lane >> 4) << 4));
    uint32_t kLane = (uint32_t)((((lane >> 4) << 3) + (lane & 7)) * FRS + (((lane >> 3) & 1) << 4));
    uint32_t vLane = (uint32_t)(((lane & 7) + ((lane >> 3) & 1) * 8) * FRS + ((lane >> 4) << 4));

    for (int kt = 0; kt < nkt; kt++) {
        if (kt + 1 < nkt) {
            flash_load_kv(sb, bh, (kt + 1) * 64, (kt + 1) & 1, tid);
            cpa_commit();
            asm volatile("cp.async.wait_group 1;" ::: "memory");
        } else {
            asm volatile("cp.async.wait_group 0;" ::: "memory");
        }
        __syncthreads();

        if (kt == 0) {
#pragma unroll
            for (int mf = 0; mf < 2; mf++)
#pragma unroll
                for (int kk = 0; kk < 4; kk++) {
                    uint32_t a = sb + FSB_Q + qAddr + (uint32_t)(mf * 16 * FRS) + kk * 32;
                    ldsm4(aQh[mf][kk], a);
                    ldsm4(aQl[mf][kk], a + FQ_B);
                }
        }

        uint32_t stg = sb + FSB_KV + (kt & 1) * FSTG_B;
        int kbase = kt * 64;

        // ---- S = Q K^T (3-term bf16, term-major per kk) ----
        float c[2][8][4];
#pragma unroll
        for (int mf = 0; mf < 2; mf++)
#pragma unroll
            for (int i = 0; i < 8; i++)
#pragma unroll
                for (int j = 0; j < 4; j++) c[mf][i][j] = 0.f;

#pragma unroll
        for (int kk = 0; kk < 4; kk++) {
            uint32_t bKh[4][4], bKl[4][4];
#pragma unroll
            for (int nf2 = 0; nf2 < 4; nf2++) {
                uint32_t ba = stg + (uint32_t)(nf2 * 16 * FRS) + kLane + kk * 32;
                ldsm4(bKh[nf2], ba);
                ldsm4(bKl[nf2], ba + FTILE);
            }
#pragma unroll
            for (int mf = 0; mf < 2; mf++)
#pragma unroll
                for (int nf = 0; nf < 8; nf++)
                    mma16816(c[mf][nf], aQh[mf][kk],
                             bKh[nf >> 1][(nf & 1) * 2], bKh[nf >> 1][(nf & 1) * 2 + 1]);
#pragma unroll
            for (int mf = 0; mf < 2; mf++)
#pragma unroll
                for (int nf = 0; nf < 8; nf++)
                    mma16816(c[mf][nf], aQh[mf][kk],
                             bKl[nf >> 1][(nf & 1) * 2], bKl[nf >> 1][(nf & 1) * 2 + 1]);
#pragma unroll
            for (int mf = 0; mf < 2; mf++)
#pragma unroll
                for (int nf = 0; nf < 8; nf++)
                    mma16816(c[mf][nf], aQl[mf][kk],
                             bKh[nf >> 1][(nf & 1) * 2], bKh[nf >> 1][(nf & 1) * 2 + 1]);
        }

        // ---- mask + exp + pack P (fp16 hi/lo) ----
        bool needmask = (kbase + 63) > (q0 + w * 32);
        uint32_t aPh[2][4][4], aPl[2][4][4];
#pragma unroll
        for (int mf = 0; mf < 2; mf++) {
            int qrA = q0 + w * 32 + mf * 16 + (lane >> 2);
#pragma unroll
            for (int nf = 0; nf < 8; nf++) {
                if (needmask) {
                    int key0 = kbase + nf * 8 + (lane & 3) * 2;
                    if (key0 > qrA)         c[mf][nf][0] = -100000.f;
                    if (key0 + 1 > qrA)     c[mf][nf][1] = -100000.f;
                    if (key0 > qrA + 8)     c[mf][nf][2] = -100000.f;
                    if (key0 + 1 > qrA + 8) c[mf][nf][3] = -100000.f;
                }
                float p0 = ex2f(c[mf][nf][0]), p1 = ex2f(c[mf][nf][1]);
                float p2 = ex2f(c[mf][nf][2]), p3 = ex2f(c[mf][nf][3]);
                ls[mf][0] += p0 + p1;
                ls[mf][1] += p2 + p3;
                __half h0 = __float2half_rn(p0), h1 = __float2half_rn(p1);
                __half h2 = __float2half_rn(p2), h3 = __float2half_rn(p3);
                int kk = nf >> 1, sl = (nf & 1) * 2;
                aPh[mf][kk][sl]     = ((uint32_t)*(uint16_t*)&h0) | (((uint32_t)*(uint16_t*)&h1) << 16);
                aPh[mf][kk][sl + 1] = ((uint32_t)*(uint16_t*)&h2) | (((uint32_t)*(uint16_t*)&h3) << 16);
                aPl[mf][kk][sl]     = pack_h2(p0 - __half2float(h0), p1 - __half2float(h1));
                aPl[mf][kk][sl + 1] = pack_h2(p2 - __half2float(h2), p3 - __half2float(h3));
            }
        }

        // ---- O += P V (2-term fp16, term-major per kk) ----
        uint32_t vstg = stg + 2 * FTILE;
#pragma unroll
        for (int kk = 0; kk < 4; kk++) {
            uint32_t vf[4][4];
#pragma unroll
            for (int df2 = 0; df2 < 4; df2++)
                ldsm4t(vf[df2], vstg + (uint32_t)(kk * 16 * FRS) + vLane + df2 * 32);
#pragma unroll
            for (int mf = 0; mf < 2; mf++)
#pragma unroll
                for (int nf = 0; nf < 8; nf++)
                    mmah(o[mf][nf], aPh[mf][kk],
                         vf[nf >> 1][(nf & 1) * 2], vf[nf >> 1][(nf & 1) * 2 + 1]);
#pragma unroll
            for (int mf = 0; mf < 2; mf++)
#pragma unroll
                for (int nf = 0; nf < 8; nf++)
                    mmah(o[mf][nf], aPl[mf][kk],
                         vf[nf >> 1][(nf & 1) * 2], vf[nf >> 1][(nf & 1) * 2 + 1]);
        }
        __syncthreads();
    }

    int b = bh >> 4, h = bh & 15;
    int colBase = h * 64 + (lane & 3) * 2;
#pragma unroll
    for (int mf = 0; mf < 2; mf++) {
        float lA = ls[mf][0], lB = ls[mf][1];
        lA += __shfl_xor_sync(0xffffffffu, lA, 1);
        lA += __shfl_xor_sync(0xffffffffu, lA, 2);
        lB += __shfl_xor_sync(0xffffffffu, lB, 1);
        lB += __shfl_xor_sync(0xffffffffu, lB, 2);
        float invA = 1.f / lA, invB = 1.f / lB;
        int rowA = b * 2048 + q0 + w * 32 + mf * 16 + (lane >> 2);
#pragma unroll
        for (int nf = 0; nf < 8; nf++) {
            int col = colBase + nf * 8;
            *(uint32_t*)(g_aof + (size_t)rowA * 1024 + col) =
                pack_h2(o[mf][nf][0] * invA, o[mf][nf][1] * invA);
            *(uint32_t*)(g_aof + (size_t)(rowA + 8) * 1024 + col) =
                pack_h2(o[mf][nf][2] * invB, o[mf][nf][3] * invB);
        }
    }
}

// ======================= launch =======================
extern "C" void kernel_launch(void* const* d_in, const int* in_sizes, int n_in,
                              void* d_out, int out_size) {
    const float* x = (const float*)d_in[0];
    const float* Wqkv = (const float*)d_in[1];
    const float* Wout = (const float*)d_in[2];
    float* out = (float*)d_out;

    void *p_xf, *p_wqf, *p_aof, *p_wof;
    cudaGetSymbolAddress(&p_xf,  g_xf);
    cudaGetSymbolAddress(&p_wqf, g_wqf);
    cudaGetSymbolAddress(&p_aof, g_aof);
    cudaGetSymbolAddress(&p_wof, g_wof);

    cudaFuncSetAttribute(gemm_mma_kernel<0>, cudaFuncAttributeMaxDynamicSharedMemorySize, GEMM_SMEM);
    cudaFuncSetAttribute(gemm_mma_kernel<1>, cudaFuncAttributeMaxDynamicSharedMemorySize, GEMM_SMEM);
    cudaFuncSetAttribute(flash_tc_kernel, cudaFuncAttributeMaxDynamicSharedMemorySize, FLASH_SMEM);

    rope_table_kernel<<<SEQ, 32>>>();

    conv_f16_kernel<<<4096, 256>>>(x, (__half*)p_xf, M_ROWS * D_MODEL);
    trans_f16_kernel<<<dim3(QKV_N / 32, D_MODEL / 32), dim3(32, 8)>>>(
        Wqkv, (__half*)p_wqf, D_MODEL, QKV_N);

    gemm_mma_kernel<0><<<dim3(QKV_N / 128, M_ROWS / 128), 128, GEMM_SMEM>>>(
        (const __half*)p_xf, (const __half*)p_wqf, nullptr);

    int rope_total = 2 * BATCH * N_HEADS * SEQ * 32;
    rope_split_kernel<<<rope_total / 256, 256>>>();

    flash_tc_kernel<<<dim3(16, 64), 128, FLASH_SMEM>>>();

    trans_f16_kernel<<<dim3(D_MODEL / 32, D_MODEL / 32), dim3(32, 8)>>>(
        Wout, (__half*)p_wof, D_MODEL, D_MODEL);

    gemm_mma_kernel<1><<<dim3(D_MODEL / 128, M_ROWS / 128), 128, GEMM_SMEM>>>(
        (const __half*)p_aof, (const __half*)p_wof, out);
}

// round 9
// speedup vs baseline: 1.8869x; 1.0291x over previous
#include <cuda_runtime.h>
#include <cuda_bf16.h>
#include <cuda_fp16.h>
#include <math.h>
#include <stdint.h>

#define D_MODEL 1024
#define N_HEADS 16
#define HEAD_DIM 64
#define BATCH 4
#define SEQ 2048
#define M_ROWS (BATCH * SEQ)          // 8192
#define QKV_N (3 * D_MODEL)           // 3072

// ======================= scratch (static device globals) =======================
__device__ __align__(16) float g_cos[SEQ * 32];
__device__ __align__(16) float g_sin[SEQ * 32];
__device__ __align__(16) __half g_xf[M_ROWS * D_MODEL];
__device__ __align__(16) __half g_wqf[D_MODEL * QKV_N];       // transposed [3072][1024]
__device__ __align__(16) __half g_aof[M_ROWS * D_MODEL];
__device__ __align__(16) __half g_wof[D_MODEL * D_MODEL];     // transposed [1024][1024]
__device__ __align__(16) __nv_bfloat16 g_qh[BATCH * N_HEADS * SEQ * HEAD_DIM];
__device__ __align__(16) __nv_bfloat16 g_ql[BATCH * N_HEADS * SEQ * HEAD_DIM];
__device__ __align__(16) __nv_bfloat16 g_kh[BATCH * N_HEADS * SEQ * HEAD_DIM];
__device__ __align__(16) __nv_bfloat16 g_kl[BATCH * N_HEADS * SEQ * HEAD_DIM];
__device__ __align__(16) __half g_vf[BATCH * N_HEADS * SEQ * HEAD_DIM];

// ======================= PTX helpers =======================
__device__ __forceinline__ uint32_t smem_to_u32(const void* smem_ptr) {
    uint32_t addr;
    asm("{ .reg .u64 tmp; cvta.to.shared.u64 tmp, %1; cvt.u32.u64 %0, tmp; }"
        : "=r"(addr) : "l"(smem_ptr));
    return addr;
}
__device__ __forceinline__ void cpa16(uint32_t s, const void* g) {
    asm volatile("cp.async.cg.shared.global [%0], [%1], 16;" :: "r"(s), "l"(g));
}
__device__ __forceinline__ void cpa_commit() {
    asm volatile("cp.async.commit_group;" ::: "memory");
}
__device__ __forceinline__ void ldsm4(uint32_t* r, uint32_t addr) {
    asm volatile("ldmatrix.sync.aligned.m8n8.x4.shared.b16 {%0,%1,%2,%3}, [%4];"
        : "=r"(r[0]), "=r"(r[1]), "=r"(r[2]), "=r"(r[3]) : "r"(addr));
}
__device__ __forceinline__ void ldsm4t(uint32_t* r, uint32_t addr) {
    asm volatile("ldmatrix.sync.aligned.m8n8.x4.trans.shared.b16 {%0,%1,%2,%3}, [%4];"
        : "=r"(r[0]), "=r"(r[1]), "=r"(r[2]), "=r"(r[3]) : "r"(addr));
}
__device__ __forceinline__ void mma16816(float* c, const uint32_t* a, uint32_t b0, uint32_t b1) {
    asm("mma.sync.aligned.m16n8k16.row.col.f32.bf16.bf16.f32 "
        "{%0,%1,%2,%3}, {%4,%5,%6,%7}, {%8,%9}, {%0,%1,%2,%3};"
        : "+f"(c[0]), "+f"(c[1]), "+f"(c[2]), "+f"(c[3])
        : "r"(a[0]), "r"(a[1]), "r"(a[2]), "r"(a[3]), "r"(b0), "r"(b1));
}
__device__ __forceinline__ void mmah(float* c, const uint32_t* a, uint32_t b0, uint32_t b1) {
    asm("mma.sync.aligned.m16n8k16.row.col.f32.f16.f16.f32 "
        "{%0,%1,%2,%3}, {%4,%5,%6,%7}, {%8,%9}, {%0,%1,%2,%3};"
        : "+f"(c[0]), "+f"(c[1]), "+f"(c[2]), "+f"(c[3])
        : "r"(a[0]), "r"(a[1]), "r"(a[2]), "r"(a[3]), "r"(b0), "r"(b1));
}
__device__ __forceinline__ uint32_t pack_h2(float a, float b) {
    __half2 h = __floats2half2_rn(a, b);
    return *(uint32_t*)&h;
}
__device__ __forceinline__ uint32_t pack_bf2(float a, float b) {
    __nv_bfloat162 h = __floats2bfloat162_rn(a, b);
    return *(uint32_t*)&h;
}
__device__ __forceinline__ float ex2f(float x) {
    float r;
    asm("ex2.approx.ftz.f32 %0, %1;" : "=f"(r) : "f"(x));
    return r;
}

// ======================= RoPE table =======================
__global__ void rope_table_kernel() {
    int t = blockIdx.x;
    int i = threadIdx.x;
    double inv = pow(10000.0, -((double)(2 * i)) / 64.0);
    double a = (double)t * inv;
    g_cos[t * 32 + i] = (float)cos(a);
    g_sin[t * 32 + i] = (float)sin(a);
}

// ======================= fp32 -> fp16 =======================
__global__ void conv_f16_kernel(const float* __restrict__ in,
                                __half* __restrict__ out, int n) {
    int i = blockIdx.x * blockDim.x + threadIdx.x;
    int stride = gridDim.x * blockDim.x;
    for (; i < n; i += stride) out[i] = __float2half_rn(in[i]);
}

// ======================= transpose fp32 -> fp16 =======================
__global__ void trans_f16_kernel(const float* __restrict__ W,
                                 __half* __restrict__ T, int K, int N) {
    __shared__ float t[32][33];
    int n = blockIdx.x * 32 + threadIdx.x;
    int k0 = blockIdx.y * 32;
#pragma unroll
    for (int r = 0; r < 32; r += 8)
        t[threadIdx.y + r][threadIdx.x] = W[(size_t)(k0 + threadIdx.y + r) * N + n];
    __syncthreads();
    int k = k0 + threadIdx.x;
#pragma unroll
    for (int r = 0; r < 32; r += 8) {
        int n2 = blockIdx.x * 32 + threadIdx.y + r;
        T[(size_t)n2 * K + k] = __float2half_rn(t[threadIdx.x][threadIdx.y + r]);
    }
}

// ======================= fp16 warp-MMA GEMM, K-stage 64, 4 warps (2x2) ==============
// rows padded to 144B (128B data + 16 pad) -> conflict-free ldmatrix
#define GTILE 18432                     // 128 rows * 144B
#define GSTG  (2 * GTILE)               // A + B per stage
#define GEMM_SMEM (2 * GSTG)            // 73728 (double buffered)

__device__ __forceinline__ void load_stage(
    uint32_t sb, const __half* __restrict__ Ah, const __half* __restrict__ Bh,
    int m0, int n0, int k0, int tid)
{
    const __half* gp[2] = { Ah, Bh };
    int rb[2] = { m0, n0 };
#pragma unroll
    for (int i = 0; i < 16; i++) {
        int ch = tid + i * 128;              // 0..2047
        int tlb = ch >> 10;
        int w2 = ch & 1023;
        int row = w2 >> 3, c16 = w2 & 7;
        cpa16(sb + tlb * GTILE + row * 144 + c16 * 16,
              gp[tlb] + (size_t)(rb[tlb] + row) * 1024 + k0 + c16 * 8);
    }
}

template <int EPI>  // 0: RoPE+split scatter to qh/ql/kh/kl + fp16 V, 1: plain fp32 store
__global__ void __launch_bounds__(128, 2) gemm_mma_kernel(
    const __half* __restrict__ Ah, const __half* __restrict__ Bh,
    float* __restrict__ Cout)
{
    extern __shared__ char dsm[];
    uint32_t sb0 = smem_to_u32(dsm);
    int tid = threadIdx.x, lane = tid & 31, wid = tid >> 5;
    int warpM = wid >> 1, warpN = wid & 1;      // 2 x 2
    int m0 = blockIdx.y * 128, n0 = blockIdx.x * 128;

    float c[4][8][4];
#pragma unroll
    for (int i = 0; i < 4; i++)
#pragma unroll
        for (int j = 0; j < 8; j++)
#pragma unroll
            for (int k = 0; k < 4; k++) c[i][j][k] = 0.f;

    uint32_t aRow = (uint32_t)((warpM * 64 + (lane & 15)) * 144 + ((lane >> 4) << 4));
    uint32_t bRow = (uint32_t)((warpN * 64 + ((lane >> 4) << 3) + (lane & 7)) * 144 +
                               (((lane >> 3) & 1) << 4));

    const int NS = 16;
    load_stage(sb0, Ah, Bh, m0, n0, 0, tid);
    cpa_commit();

    for (int s = 0; s < NS; s++) {
        uint32_t sb = sb0 + (uint32_t)((s & 1) * GSTG);
        if (s + 1 < NS) {
            load_stage(sb0 + (uint32_t)(((s + 1) & 1) * GSTG),
                       Ah, Bh, m0, n0, (s + 1) * 64, tid);
            cpa_commit();
            asm volatile("cp.async.wait_group 1;" ::: "memory");
        } else {
            asm volatile("cp.async.wait_group 0;" ::: "memory");
        }
        __syncthreads();

#pragma unroll
        for (int k16 = 0; k16 < 4; k16++) {
            uint32_t koff = (uint32_t)(k16 * 32);
            uint32_t af[4][4], bf[4][4];
#pragma unroll
            for (int mf = 0; mf < 4; mf++)
                ldsm4(af[mf], sb + aRow + (uint32_t)(mf * 2304) + koff);
#pragma unroll
            for (int nf2 = 0; nf2 < 4; nf2++)
                ldsm4(bf[nf2], sb + GTILE + bRow + (uint32_t)(nf2 * 2304) + koff);
#pragma unroll
            for (int mf = 0; mf < 4; mf++)
#pragma unroll
                for (int nf = 0; nf < 8; nf++)
                    mmah(c[mf][nf], af[mf],
                         bf[nf >> 1][(nf & 1) * 2], bf[nf >> 1][(nf & 1) * 2 + 1]);
        }
        __syncthreads();
    }

    // ---------------- epilogue ----------------
    int mBase = m0 + warpM * 64 + (lane >> 2);
    if (EPI == 1) {
        int nBase = n0 + warpN * 64 + (lane & 3) * 2;
#pragma unroll
        for (int mf = 0; mf < 4; mf++)
#pragma unroll
            for (int nf = 0; nf < 8; nf++) {
                int row = mBase + mf * 16;
                int col = nBase + nf * 8;
                *(float2*)(Cout + (size_t)row * 1024 + col) =
                    make_float2(c[mf][nf][0], c[mf][nf][1]);
                *(float2*)(Cout + (size_t)(row + 8) * 1024 + col) =
                    make_float2(c[mf][nf][2], c[mf][nf][3]);
            }
        return;
    }

    // EPI==0: this warp's 64-col span = exactly one (sel, head)
    int col0 = n0 + warpN * 64;
    int sel = col0 >> 10;                 // 0:Q 1:K 2:V
    int h = (col0 >> 6) & 15;
    int lc = (lane & 3) * 2;

    if (sel == 2) {
        // V: straight fp16
#pragma unroll
        for (int mf = 0; mf < 4; mf++) {
            int row = mBase + mf * 16;
            int b = row >> 11, t = row & 2047;
            size_t base = ((size_t)((b * 16 + h) * 2048)) * 64;
#pragma unroll
            for (int nf = 0; nf < 8; nf++) {
                int d = lc + nf * 8;
                *(uint32_t*)(g_vf + base + (size_t)t * 64 + d) =
                    pack_h2(c[mf][nf][0], c[mf][nf][1]);
                *(uint32_t*)(g_vf + base + (size_t)(t + 8) * 64 + d) =
                    pack_h2(c[mf][nf][2], c[mf][nf][3]);
            }
        }
    } else {
        // Q/K: RoPE in registers, then bf16 hi/lo split.
        // dim d = lc + nfp*8 (<32) pairs with d+32 held in fragment nfp+4 of same lane.
        const float SCQ = 0.125f * 1.44269504088896f;
        float scale = (sel == 0) ? SCQ : 1.f;
        __nv_bfloat16* Gh = (sel == 0) ? g_qh : g_kh;
        __nv_bfloat16* Gl = (sel == 0) ? g_ql : g_kl;
#pragma unroll
        for (int mf = 0; mf < 4; mf++) {
            int row = mBase + mf * 16;
            int b = row >> 11, t = row & 2047;
            size_t base = ((size_t)((b * 16 + h) * 2048)) * 64;
#pragma unroll
            for (int nfp = 0; nfp < 4; nfp++) {
                int i0 = lc + nfp * 8;
                float2 cs0 = *(const float2*)&g_cos[t * 32 + i0];
                float2 sn0 = *(const float2*)&g_sin[t * 32 + i0];
                float2 cs8 = *(const float2*)&g_cos[(t + 8) * 32 + i0];
                float2 sn8 = *(const float2*)&g_sin[(t + 8) * 32 + i0];
#pragma unroll
                for (int rr = 0; rr < 2; rr++) {
                    float cx = rr ? cs8.x : cs0.x, cy = rr ? cs8.y : cs0.y;
                    float sx = rr ? sn8.x : sn0.x, sy = rr ? sn8.y : sn0.y;
                    float x1a = c[mf][nfp][rr * 2],     x1b = c[mf][nfp][rr * 2 + 1];
                    float x2a = c[mf][nfp + 4][rr * 2], x2b = c[mf][nfp + 4][rr * 2 + 1];
                    float r1a = (x1a * cx - x2a * sx) * scale;
                    float r1b = (x1b * cy - x2b * sy) * scale;
                    float r2a = (x2a * cx + x1a * sx) * scale;
                    float r2b = (x2b * cy + x1b * sy) * scale;
                    __nv_bfloat16 h1a = __float2bfloat16(r1a), h1b = __float2bfloat16(r1b);
                    __nv_bfloat16 h2a = __float2bfloat16(r2a), h2b = __float2bfloat16(r2b);
                    size_t off = base + (size_t)(t + rr * 8) * 64 + i0;
                    *(uint32_t*)(Gh + off) =
                        ((uint32_t)*(uint16_t*)&h1a) | (((uint32_t)*(uint16_t*)&h1b) << 16);
                    *(uint32_t*)(Gh + off + 32) =
                        ((uint32_t)*(uint16_t*)&h2a) | (((uint32_t)*(uint16_t*)&h2b) << 16);
                    *(uint32_t*)(Gl + off) =
                        pack_bf2(r1a - __bfloat162float(h1a), r1b - __bfloat162float(h1b));
                    *(uint32_t*)(Gl + off + 32) =
                        pack_bf2(r2a - __bfloat162float(h2a), r2b - __bfloat162float(h2b));
                }
            }
        }
    }
}

// ======================= Tensor-core flash: 4 warps x 32 q-rows =======================
// S = QK^T : 3-term bf16.  O = PV : 2-term fp16 (P split hi/lo, V single).
#define FRS 144
#define FTILE (64 * FRS)                 // 9216
#define FQ_B  (128 * FRS)                // 18432
#define FSB_Q 0
#define FSB_KV (2 * FQ_B)                // 36864
#define FSTG_B (3 * FTILE)               // Khi, Klo, Vf = 27648
#define FLASH_SMEM (FSB_KV + 2 * FSTG_B) // 92160

__device__ __forceinline__ void flash_load_q(uint32_t sb, int bh, int q0, int tid) {
#pragma unroll
    for (int i = 0; i < 16; i++) {
        int ch = tid + i * 128;               // 0..2047
        int tl = ch >> 10;
        int r = (ch >> 3) & 127, c16 = ch & 7;
        const __nv_bfloat16* src = (tl ? g_ql : g_qh) +
            ((size_t)bh * SEQ + q0 + r) * 64 + c16 * 8;
        cpa16(sb + FSB_Q + tl * FQ_B + r * FRS + c16 * 16, src);
    }
}
__device__ __forceinline__ void flash_load_kv(uint32_t sb, int bh, int kbase, int stg, int tid) {
    uint32_t d0 = sb + FSB_KV + stg * FSTG_B;
#pragma unroll
    for (int i = 0; i < 12; i++) {
        int ch = tid + i * 128;               // 0..1535
        int tl = ch >> 9;                     // 0 Khi, 1 Klo, 2 Vf
        int r = (ch >> 3) & 63, c16 = ch & 7;
        const void* src;
        if (tl == 0)      src = g_kh + ((size_t)bh * SEQ + kbase + r) * 64 + c16 * 8;
        else if (tl == 1) src = g_kl + ((size_t)bh * SEQ + kbase + r) * 64 + c16 * 8;
        else              src = g_vf + ((size_t)bh * SEQ + kbase + r) * 64 + c16 * 8;
        cpa16(d0 + tl * FTILE + r * FRS + c16 * 16, src);
    }
}

__global__ void __launch_bounds__(128, 2) flash_tc_kernel() {
    extern __shared__ char dsm[];
    uint32_t sb = smem_to_u32(dsm);
    int tid = threadIdx.x, lane = tid & 31, w = tid >> 5;
    int qt = 15 - (int)blockIdx.x;
    int bh = blockIdx.y;
    int q0 = qt * 128;
    int nkt = qt * 2 + 2;

    flash_load_q(sb, bh, q0, tid);
    flash_load_kv(sb, bh, 0, 0, tid);
    cpa_commit();

    uint32_t aQh[2][4][4], aQl[2][4][4];
    float o[2][8][4];
#pragma unroll
    for (int mf = 0; mf < 2; mf++)
#pragma unroll
        for (int i = 0; i < 8; i++)
#pragma unroll
            for (int j = 0; j < 4; j++) o[mf][i][j] = 0.f;
    float ls[2][2] = {{0.f, 0.f}, {0.f, 0.f}};

    uint32_t qAddr = (uint32_t)((w * 32 + (lane & 15)) * FRS + ((lane >> 4) << 4));
    uint32_t kLane = (uint32_t)((((lane >> 4) << 3) + (lane & 7)) * FRS + (((lane >> 3) & 1) << 4));
    uint32_t vLane = (uint32_t)(((lane & 7) + ((lane >> 3) & 1) * 8) * FRS + ((lane >> 4) << 4));

    for (int kt = 0; kt < nkt; kt++) {
        if (kt + 1 < nkt) {
            flash_load_kv(sb, bh, (kt + 1) * 64, (kt + 1) & 1, tid);
            cpa_commit();
            asm volatile("cp.async.wait_group 1;" ::: "memory");
        } else {
            asm volatile("cp.async.wait_group 0;" ::: "memory");
        }
        __syncthreads();

        if (kt == 0) {
#pragma unroll
            for (int mf = 0; mf < 2; mf++)
#pragma unroll
                for (int kk = 0; kk < 4; kk++) {
                    uint32_t a = sb + FSB_Q + qAddr + (uint32_t)(mf * 16 * FRS) + kk * 32;
                    ldsm4(aQh[mf][kk], a);
                    ldsm4(aQl[mf][kk], a + FQ_B);
                }
        }

        uint32_t stg = sb + FSB_KV + (kt & 1) * FSTG_B;
        int kbase = kt * 64;

        // ---- S = Q K^T (3-term bf16, term-major per kk) ----
        float c[2][8][4];
#pragma unroll
        for (int mf = 0; mf < 2; mf++)
#pragma unroll
            for (int i = 0; i < 8; i++)
#pragma unroll
                for (int j = 0; j < 4; j++) c[mf][i][j] = 0.f;

#pragma unroll
        for (int kk = 0; kk < 4; kk++) {
            uint32_t bKh[4][4], bKl[4][4];
#pragma unroll
            for (int nf2 = 0; nf2 < 4; nf2++) {
                uint32_t ba = stg + (uint32_t)(nf2 * 16 * FRS) + kLane + kk * 32;
                ldsm4(bKh[nf2], ba);
                ldsm4(bKl[nf2], ba + FTILE);
            }
#pragma unroll
            for (int mf = 0; mf < 2; mf++)
#pragma unroll
                for (int nf = 0; nf < 8; nf++)
                    mma16816(c[mf][nf], aQh[mf][kk],
                             bKh[nf >> 1][(nf & 1) * 2], bKh[nf >> 1][(nf & 1) * 2 + 1]);
#pragma unroll
            for (int mf = 0; mf < 2; mf++)
#pragma unroll
                for (int nf = 0; nf < 8; nf++)
                    mma16816(c[mf][nf], aQh[mf][kk],
                             bKl[nf >> 1][(nf & 1) * 2], bKl[nf >> 1][(nf & 1) * 2 + 1]);
#pragma unroll
            for (int mf = 0; mf < 2; mf++)
#pragma unroll
                for (int nf = 0; nf < 8; nf++)
                    mma16816(c[mf][nf], aQl[mf][kk],
                             bKh[nf >> 1][(nf & 1) * 2], bKh[nf >> 1][(nf & 1) * 2 + 1]);
        }

        // ---- mask + exp + pack P (fp16 hi/lo) ----
        bool needmask = (kbase + 63) > (q0 + w * 32);
        uint32_t aPh[2][4][4], aPl[2][4][4];
#pragma unroll
        for (int mf = 0; mf < 2; mf++) {
            int qrA = q0 + w * 32 + mf * 16 + (lane >> 2);
#pragma unroll
            for (int nf = 0; nf < 8; nf++) {
                if (needmask) {
                    int key0 = kbase + nf * 8 + (lane & 3) * 2;
                    if (key0 > qrA)         c[mf][nf][0] = -100000.f;
                    if (key0 + 1 > qrA)     c[mf][nf][1] = -100000.f;
                    if (key0 > qrA + 8)     c[mf][nf][2] = -100000.f;
                    if (key0 + 1 > qrA + 8) c[mf][nf][3] = -100000.f;
                }
                float p0 = ex2f(c[mf][nf][0]), p1 = ex2f(c[mf][nf][1]);
                float p2 = ex2f(c[mf][nf][2]), p3 = ex2f(c[mf][nf][3]);
                ls[mf][0] += p0 + p1;
                ls[mf][1] += p2 + p3;
                __half h0 = __float2half_rn(p0), h1 = __float2half_rn(p1);
                __half h2 = __float2half_rn(p2), h3 = __float2half_rn(p3);
                int kk = nf >> 1, sl = (nf & 1) * 2;
                aPh[mf][kk][sl]     = ((uint32_t)*(uint16_t*)&h0) | (((uint32_t)*(uint16_t*)&h1) << 16);
                aPh[mf][kk][sl + 1] = ((uint32_t)*(uint16_t*)&h2) | (((uint32_t)*(uint16_t*)&h3) << 16);
                aPl[mf][kk][sl]     = pack_h2(p0 - __half2float(h0), p1 - __half2float(h1));
                aPl[mf][kk][sl + 1] = pack_h2(p2 - __half2float(h2), p3 - __half2float(h3));
            }
        }

        // ---- O += P V (2-term fp16, term-major per kk) ----
        uint32_t vstg = stg + 2 * FTILE;
#pragma unroll
        for (int kk = 0; kk < 4; kk++) {
            uint32_t vf[4][4];
#pragma unroll
            for (int df2 = 0; df2 < 4; df2++)
                ldsm4t(vf[df2], vstg + (uint32_t)(kk * 16 * FRS) + vLane + df2 * 32);
#pragma unroll
            for (int mf = 0; mf < 2; mf++)
#pragma unroll
                for (int nf = 0; nf < 8; nf++)
                    mmah(o[mf][nf], aPh[mf][kk],
                         vf[nf >> 1][(nf & 1) * 2], vf[nf >> 1][(nf & 1) * 2 + 1]);
#pragma unroll
            for (int mf = 0; mf < 2; mf++)
#pragma unroll
                for (int nf = 0; nf < 8; nf++)
                    mmah(o[mf][nf], aPl[mf][kk],
                         vf[nf >> 1][(nf & 1) * 2], vf[nf >> 1][(nf & 1) * 2 + 1]);
        }
        __syncthreads();
    }

    int b = bh >> 4, h = bh & 15;
    int colBase = h * 64 + (lane & 3) * 2;
#pragma unroll
    for (int mf = 0; mf < 2; mf++) {
        float lA = ls[mf][0], lB = ls[mf][1];
        lA += __shfl_xor_sync(0xffffffffu, lA, 1);
        lA += __shfl_xor_sync(0xffffffffu, lA, 2);
        lB += __shfl_xor_sync(0xffffffffu, lB, 1);
        lB += __shfl_xor_sync(0xffffffffu, lB, 2);
        float invA = 1.f / lA, invB = 1.f / lB;
        int rowA = b * 2048 + q0 + w * 32 + mf * 16 + (lane >> 2);
#pragma unroll
        for (int nf = 0; nf < 8; nf++) {
            int col = colBase + nf * 8;
            *(uint32_t*)(g_aof + (size_t)rowA * 1024 + col) =
                pack_h2(o[mf][nf][0] * invA, o[mf][nf][1] * invA);
            *(uint32_t*)(g_aof + (size_t)(rowA + 8) * 1024 + col) =
                pack_h2(o[mf][nf][2] * invB, o[mf][nf][3] * invB);
        }
    }
}

// ======================= launch =======================
extern "C" void kernel_launch(void* const* d_in, const int* in_sizes, int n_in,
                              void* d_out, int out_size) {
    const float* x = (const float*)d_in[0];
    const float* Wqkv = (const float*)d_in[1];
    const float* Wout = (const float*)d_in[2];
    float* out = (float*)d_out;

    void *p_xf, *p_wqf, *p_aof, *p_wof;
    cudaGetSymbolAddress(&p_xf,  g_xf);
    cudaGetSymbolAddress(&p_wqf, g_wqf);
    cudaGetSymbolAddress(&p_aof, g_aof);
    cudaGetSymbolAddress(&p_wof, g_wof);

    cudaFuncSetAttribute(gemm_mma_kernel<0>, cudaFuncAttributeMaxDynamicSharedMemorySize, GEMM_SMEM);
    cudaFuncSetAttribute(gemm_mma_kernel<1>, cudaFuncAttributeMaxDynamicSharedMemorySize, GEMM_SMEM);
    cudaFuncSetAttribute(flash_tc_kernel, cudaFuncAttributeMaxDynamicSharedMemorySize, FLASH_SMEM);

    rope_table_kernel<<<SEQ, 32>>>();     // must precede gemm<0> (epilogue RoPE)

    conv_f16_kernel<<<4096, 256>>>(x, (__half*)p_xf, M_ROWS * D_MODEL);
    trans_f16_kernel<<<dim3(QKV_N / 32, D_MODEL / 32), dim3(32, 8)>>>(
        Wqkv, (__half*)p_wqf, D_MODEL, QKV_N);

    gemm_mma_kernel<0><<<dim3(QKV_N / 128, M_ROWS / 128), 128, GEMM_SMEM>>>(
        (const __half*)p_xf, (const __half*)p_wqf, nullptr);

    flash_tc_kernel<<<dim3(16, 64), 128, FLASH_SMEM>>>();

    trans_f16_kernel<<<dim3(D_MODEL / 32, D_MODEL / 32), dim3(32, 8)>>>(
        Wout, (__half*)p_wof, D_MODEL, D_MODEL);

    gemm_mma_kernel<1><<<dim3(D_MODEL / 128, M_ROWS / 128), 128, GEMM_SMEM>>>(
        (const __half*)p_aof, (const __half*)p_wof, out);
}